// round 1
// baseline (speedup 1.0000x reference)
#include <cuda_runtime.h>
#include <mma.h>

using namespace nvcuda;

#define BB 4
#define TT 2048
#define CC 1024
#define NH 16
#define HS 64

// ---------------- scratch (allocation-free: __device__ globals) -------------
__device__ float g_q[BB * TT * CC];   // (B,H,T,D)
__device__ float g_k[BB * TT * CC];   // (B,H,T,D)
__device__ float g_v[BB * TT * CC];   // (B,H,T,D)
__device__ float g_y[BB * TT * CC];   // (B,T,C)

__device__ __forceinline__ float cvt_tf32(float x) {
    return wmma::__float_to_tf32(x);
}

// ============================================================================
// GEMM: out[M=8192, N=1024] = A[8192x1024] * W[1024x1024] + bias
// split==1: out written as (B,H,T,D); split==0: row-major (B,T,C).
// Tiles: BM=128, BN=128, BK=16. 256 threads = 8 warps (2x4), each warp 64x32.
// ============================================================================
#define GBM 128
#define GBN 128
#define GBK 16

__global__ __launch_bounds__(256) void gemm_tf32_kernel(
    const float* __restrict__ A, const float* __restrict__ W,
    const float* __restrict__ bias, float* __restrict__ out, int split)
{
    __shared__ float As[GBM * GBK];        // ld = 16
    __shared__ float Bs[GBK * GBN];        // ld = 128
    __shared__ float stage[8 * 16 * 20];   // per-warp 16x16 staging (ld=20)

    const int tid  = threadIdx.x;
    const int wid  = tid >> 5;
    const int lane = tid & 31;

    const int m0 = blockIdx.y * GBM;
    const int n0 = blockIdx.x * GBN;

    const int warp_m = wid >> 2;   // 0..1 -> 64 rows each
    const int warp_n = wid & 3;    // 0..3 -> 32 cols each

    wmma::fragment<wmma::accumulator, 16, 16, 8, float> acc[4][2];
#pragma unroll
    for (int i = 0; i < 4; i++)
#pragma unroll
        for (int j = 0; j < 2; j++)
            wmma::fill_fragment(acc[i][j], 0.0f);

    for (int k0 = 0; k0 < CC; k0 += GBK) {
        // load A tile: 128 rows x 16 cols = 512 float4
#pragma unroll
        for (int i = tid; i < 512; i += 256) {
            int row = i >> 2;
            int c4  = i & 3;
            float4 t4 = *(const float4*)(A + (size_t)(m0 + row) * CC + k0 + c4 * 4);
            float* dst = As + row * GBK + c4 * 4;
            dst[0] = cvt_tf32(t4.x); dst[1] = cvt_tf32(t4.y);
            dst[2] = cvt_tf32(t4.z); dst[3] = cvt_tf32(t4.w);
        }
        // load B tile: 16 rows x 128 cols = 512 float4
#pragma unroll
        for (int i = tid; i < 512; i += 256) {
            int row = i >> 5;
            int c4  = i & 31;
            float4 t4 = *(const float4*)(W + (size_t)(k0 + row) * CC + n0 + c4 * 4);
            float* dst = Bs + row * GBN + c4 * 4;
            dst[0] = cvt_tf32(t4.x); dst[1] = cvt_tf32(t4.y);
            dst[2] = cvt_tf32(t4.z); dst[3] = cvt_tf32(t4.w);
        }
        __syncthreads();

#pragma unroll
        for (int kk = 0; kk < GBK; kk += 8) {
            wmma::fragment<wmma::matrix_a, 16, 16, 8, wmma::precision::tf32, wmma::row_major> af[4];
            wmma::fragment<wmma::matrix_b, 16, 16, 8, wmma::precision::tf32, wmma::row_major> bf[2];
#pragma unroll
            for (int i = 0; i < 4; i++)
                wmma::load_matrix_sync(af[i], As + (warp_m * 64 + i * 16) * GBK + kk, GBK);
#pragma unroll
            for (int j = 0; j < 2; j++)
                wmma::load_matrix_sync(bf[j], Bs + kk * GBN + warp_n * 32 + j * 16, GBN);
#pragma unroll
            for (int i = 0; i < 4; i++)
#pragma unroll
                for (int j = 0; j < 2; j++)
                    wmma::mma_sync(acc[i][j], af[i], bf[j], acc[i][j]);
        }
        __syncthreads();
    }

    // epilogue: stage each 16x16 through smem, add bias, scatter
    float* st = stage + wid * 16 * 20;
#pragma unroll
    for (int i = 0; i < 4; i++) {
#pragma unroll
        for (int j = 0; j < 2; j++) {
            wmma::store_matrix_sync(st, acc[i][j], 20, wmma::mem_row_major);
            __syncwarp();
            int row0 = m0 + warp_m * 64 + i * 16;
            int col0 = n0 + warp_n * 32 + j * 16;
#pragma unroll
            for (int e = lane; e < 256; e += 32) {
                int r = e >> 4, c = e & 15;
                int m = row0 + r, n = col0 + c;
                float val = st[r * 20 + c] + bias[n];
                if (split) {
                    int b = m >> 11, t = m & 2047;
                    int h = n >> 6,  d = n & 63;
                    out[((((size_t)b * NH + h) * TT + t) << 6) + d] = val;
                } else {
                    out[(size_t)m * CC + n] = val;
                }
            }
            __syncwarp();
        }
    }
}

// ============================================================================
// Flash attention (causal, online softmax). One block per (b, h, 64-row qtile).
// 256 threads = 8 warps. smem tiles ld=72 (pad). tf32 wmma for QK^T and PV.
// ============================================================================
#define LDS 72
#define ATT_SMEM_BYTES (5 * 64 * LDS * 4 + 3 * 64 * 4)

__global__ __launch_bounds__(256) void attn_kernel(
    const float* __restrict__ q, const float* __restrict__ k,
    const float* __restrict__ v, float* __restrict__ y)
{
    extern __shared__ float sm[];
    float* Qs = sm;                  // 64 x 72
    float* Ks = Qs + 64 * LDS;       // 64 x 72
    float* Vs = Ks + 64 * LDS;       // 64 x 72
    float* Ss = Vs + 64 * LDS;       // 64 x 72 (scores / probs)
    float* Os = Ss + 64 * LDS;       // 64 x 72 (output accumulator, fp32)
    float* m_s  = Os + 64 * LDS;     // 64
    float* l_s  = m_s + 64;          // 64
    float* al_s = l_s + 64;          // 64

    const int qt = blockIdx.x;
    const int h  = blockIdx.y;
    const int b  = blockIdx.z;
    const int tid  = threadIdx.x;
    const int wid  = tid >> 5;

    const size_t head_base = ((size_t)b * NH + h) * TT * HS;
    const float* qb  = q + head_base + (size_t)qt * 64 * HS;
    const float* kb0 = k + head_base;
    const float* vb0 = v + head_base;

    // load Q (scaled by 1/sqrt(64)=0.125, tf32-rounded)
#pragma unroll
    for (int i = tid; i < 1024; i += 256) {
        int r = i >> 4, c4 = i & 15;
        float4 t4 = *(const float4*)(qb + r * HS + c4 * 4);
        float* dst = Qs + r * LDS + c4 * 4;
        dst[0] = cvt_tf32(t4.x * 0.125f); dst[1] = cvt_tf32(t4.y * 0.125f);
        dst[2] = cvt_tf32(t4.z * 0.125f); dst[3] = cvt_tf32(t4.w * 0.125f);
    }
    for (int i = tid; i < 64 * LDS; i += 256) Os[i] = 0.0f;
    if (tid < 64) { m_s[tid] = -1e30f; l_s[tid] = 0.0f; }
    __syncthreads();

    const int warp_m = wid >> 1;   // 0..3 -> 16 rows
    const int warp_n = wid & 1;    // 0..1 -> 32 cols

    for (int kt = 0; kt <= qt; kt++) {
        // load K, V tiles (tf32)
        const float* kb = kb0 + (size_t)kt * 64 * HS;
        const float* vb = vb0 + (size_t)kt * 64 * HS;
#pragma unroll
        for (int i = tid; i < 1024; i += 256) {
            int r = i >> 4, c4 = i & 15;
            float4 tk = *(const float4*)(kb + r * HS + c4 * 4);
            float4 tv = *(const float4*)(vb + r * HS + c4 * 4);
            float* dk = Ks + r * LDS + c4 * 4;
            float* dv = Vs + r * LDS + c4 * 4;
            dk[0] = cvt_tf32(tk.x); dk[1] = cvt_tf32(tk.y);
            dk[2] = cvt_tf32(tk.z); dk[3] = cvt_tf32(tk.w);
            dv[0] = cvt_tf32(tv.x); dv[1] = cvt_tf32(tv.y);
            dv[2] = cvt_tf32(tv.z); dv[3] = cvt_tf32(tv.w);
        }
        __syncthreads();

        // S = Q * K^T  (64x64)
        {
            wmma::fragment<wmma::accumulator, 16, 16, 8, float> sacc[2];
#pragma unroll
            for (int j = 0; j < 2; j++) wmma::fill_fragment(sacc[j], 0.0f);
#pragma unroll
            for (int d = 0; d < HS; d += 8) {
                wmma::fragment<wmma::matrix_a, 16, 16, 8, wmma::precision::tf32, wmma::row_major> af;
                wmma::load_matrix_sync(af, Qs + (warp_m * 16) * LDS + d, LDS);
#pragma unroll
                for (int j = 0; j < 2; j++) {
                    wmma::fragment<wmma::matrix_b, 16, 16, 8, wmma::precision::tf32, wmma::col_major> bf;
                    wmma::load_matrix_sync(bf, Ks + (warp_n * 32 + j * 16) * LDS + d, LDS);
                    wmma::mma_sync(sacc[j], af, bf, sacc[j]);
                }
            }
#pragma unroll
            for (int j = 0; j < 2; j++)
                wmma::store_matrix_sync(Ss + (warp_m * 16) * LDS + warp_n * 32 + j * 16,
                                        sacc[j], LDS, wmma::mem_row_major);
        }
        __syncthreads();

        // causal mask on the diagonal tile
        if (kt == qt) {
#pragma unroll
            for (int i = tid; i < 4096; i += 256) {
                int r = i >> 6, c = i & 63;
                if (c > r) Ss[r * LDS + c] = -1e30f;
            }
            __syncthreads();
        }

        // online softmax update: row = tid/4, 4 lanes x 16 cols per row
        {
            const int r   = tid >> 2;
            const int sub = tid & 3;
            float mx = -1e30f;
#pragma unroll
            for (int c = sub * 16; c < sub * 16 + 16; c++)
                mx = fmaxf(mx, Ss[r * LDS + c]);
            mx = fmaxf(mx, __shfl_xor_sync(0xffffffffu, mx, 1));
            mx = fmaxf(mx, __shfl_xor_sync(0xffffffffu, mx, 2));
            if (sub == 0) {
                float mo = m_s[r];
                float mn = fmaxf(mo, mx);
                float a  = __expf(mo - mn);
                m_s[r]  = mn;
                al_s[r] = a;
                l_s[r] *= a;
            }
            __syncthreads();

            float mn = m_s[r];
            float a  = al_s[r];
            float s  = 0.0f;
#pragma unroll
            for (int c = sub * 16; c < sub * 16 + 16; c++) {
                float p = __expf(Ss[r * LDS + c] - mn);
                s += p;
                Ss[r * LDS + c] = cvt_tf32(p);
            }
            s += __shfl_xor_sync(0xffffffffu, s, 1);
            s += __shfl_xor_sync(0xffffffffu, s, 2);
            if (sub == 0) l_s[r] += s;
            // rescale O row
#pragma unroll
            for (int c = sub * 16; c < sub * 16 + 16; c++)
                Os[r * LDS + c] *= a;
        }
        __syncthreads();

        // O += P * V
        {
            wmma::fragment<wmma::accumulator, 16, 16, 8, float> oacc[2];
#pragma unroll
            for (int j = 0; j < 2; j++)
                wmma::load_matrix_sync(oacc[j],
                    Os + (warp_m * 16) * LDS + warp_n * 32 + j * 16, LDS, wmma::mem_row_major);
#pragma unroll
            for (int kk = 0; kk < 64; kk += 8) {
                wmma::fragment<wmma::matrix_a, 16, 16, 8, wmma::precision::tf32, wmma::row_major> af;
                wmma::load_matrix_sync(af, Ss + (warp_m * 16) * LDS + kk, LDS);
#pragma unroll
                for (int j = 0; j < 2; j++) {
                    wmma::fragment<wmma::matrix_b, 16, 16, 8, wmma::precision::tf32, wmma::row_major> bf;
                    wmma::load_matrix_sync(bf, Vs + kk * LDS + warp_n * 32 + j * 16, LDS);
                    wmma::mma_sync(oacc[j], af, bf, oacc[j]);
                }
            }
#pragma unroll
            for (int j = 0; j < 2; j++)
                wmma::store_matrix_sync(Os + (warp_m * 16) * LDS + warp_n * 32 + j * 16,
                                        oacc[j], LDS, wmma::mem_row_major);
        }
        __syncthreads();
    }

    // normalize and write y (B,T,C) row-major
    for (int i = tid; i < 4096; i += 256) {
        int r = i >> 6, c = i & 63;
        float val = Os[r * LDS + c] / l_s[r];
        y[((size_t)b * TT + (size_t)qt * 64 + r) * CC + (size_t)h * HS + c] = val;
    }
}

// ============================================================================
// launch
// ============================================================================
extern "C" void kernel_launch(void* const* d_in, const int* in_sizes, int n_in,
                              void* d_out, int out_size)
{
    const float* x  = (const float*)d_in[0];
    const float* Wk = (const float*)d_in[1];
    const float* bk = (const float*)d_in[2];
    const float* Wq = (const float*)d_in[3];
    const float* bq = (const float*)d_in[4];
    const float* Wv = (const float*)d_in[5];
    const float* bv = (const float*)d_in[6];
    const float* Wo = (const float*)d_in[7];
    const float* bo = (const float*)d_in[8];
    float* out = (float*)d_out;

    float *qp, *kp, *vp, *yp;
    cudaGetSymbolAddress((void**)&qp, g_q);
    cudaGetSymbolAddress((void**)&kp, g_k);
    cudaGetSymbolAddress((void**)&vp, g_v);
    cudaGetSymbolAddress((void**)&yp, g_y);

    cudaFuncSetAttribute(attn_kernel, cudaFuncAttributeMaxDynamicSharedMemorySize,
                         ATT_SMEM_BYTES);

    dim3 ggrid(CC / GBN, (BB * TT) / GBM);
    gemm_tf32_kernel<<<ggrid, 256>>>(x, Wq, bq, qp, 1);
    gemm_tf32_kernel<<<ggrid, 256>>>(x, Wk, bk, kp, 1);
    gemm_tf32_kernel<<<ggrid, 256>>>(x, Wv, bv, vp, 1);

    dim3 agrid(TT / 64, NH, BB);
    attn_kernel<<<agrid, 256, ATT_SMEM_BYTES>>>(qp, kp, vp, yp);

    gemm_tf32_kernel<<<ggrid, 256>>>(yp, Wo, bo, out, 0);
}

// round 2
// speedup vs baseline: 1.5655x; 1.5655x over previous
#include <cuda_runtime.h>
#include <mma.h>
#include <cstdint>

using namespace nvcuda;

#define BB 4
#define TT 2048
#define CC 1024
#define NH 16
#define HS 64

// ---------------- scratch (allocation-free: __device__ globals) -------------
__device__ float g_q[BB * TT * CC];   // (B,H,T,D)
__device__ float g_k[BB * TT * CC];   // (B,H,T,D)
__device__ float g_v[BB * TT * CC];   // (B,H,T,D)
__device__ float g_y[BB * TT * CC];   // (B,T,C)

__device__ __forceinline__ float cvt_tf32(float x) {
    return wmma::__float_to_tf32(x);
}
__device__ __forceinline__ uint32_t cvt_tf32_u(float x) {
    return __float_as_uint(wmma::__float_to_tf32(x));
}

// ============================================================================
// GEMM: out[8192,1024] = A[8192x1024]*W[1024x1024] + bias. Double-buffered.
// split==1: out written as (B,H,T,D); split==0: row-major (B,T,C).
// BM=128, BN=128, BK=16. 256 threads = 8 warps (2x4), warp tile 64x32.
// ============================================================================
#define GBK 16
#define ALD 20
#define BLD 132

__global__ __launch_bounds__(256) void gemm_tf32_kernel(
    const float* __restrict__ A, const float* __restrict__ W,
    const float* __restrict__ bias, float* __restrict__ out, int split)
{
    __shared__ float As[2][128 * ALD];
    __shared__ float Bs[2][GBK * BLD];
    __shared__ float stage[8 * 16 * 20];

    const int tid  = threadIdx.x;
    const int wid  = tid >> 5;
    const int lane = tid & 31;

    const int m0 = blockIdx.y * 128;
    const int n0 = blockIdx.x * 128;

    const int warp_m = wid >> 2;   // 0..1 -> 64 rows
    const int warp_n = wid & 3;    // 0..3 -> 32 cols

    // prefetch register staging
    float4 pa[2], pb[2];
    const int a_row0 = tid >> 2,        a_c4 = tid & 3;
    const int a_row1 = (tid + 256) >> 2;
    const int b_row0 = tid >> 5,        b_c4 = tid & 31;
    const int b_row1 = (tid + 256) >> 5;

#define G_LOAD(K0)                                                              \
    do {                                                                        \
        pa[0] = *(const float4*)(A + (size_t)(m0 + a_row0) * CC + (K0) + a_c4 * 4); \
        pa[1] = *(const float4*)(A + (size_t)(m0 + a_row1) * CC + (K0) + a_c4 * 4); \
        pb[0] = *(const float4*)(W + (size_t)((K0) + b_row0) * CC + n0 + b_c4 * 4); \
        pb[1] = *(const float4*)(W + (size_t)((K0) + b_row1) * CC + n0 + b_c4 * 4); \
    } while (0)

#define G_STS(BUF)                                                              \
    do {                                                                        \
        float* da0 = As[BUF] + a_row0 * ALD + a_c4 * 4;                         \
        da0[0] = cvt_tf32(pa[0].x); da0[1] = cvt_tf32(pa[0].y);                 \
        da0[2] = cvt_tf32(pa[0].z); da0[3] = cvt_tf32(pa[0].w);                 \
        float* da1 = As[BUF] + a_row1 * ALD + a_c4 * 4;                         \
        da1[0] = cvt_tf32(pa[1].x); da1[1] = cvt_tf32(pa[1].y);                 \
        da1[2] = cvt_tf32(pa[1].z); da1[3] = cvt_tf32(pa[1].w);                 \
        float* db0 = Bs[BUF] + b_row0 * BLD + b_c4 * 4;                         \
        db0[0] = cvt_tf32(pb[0].x); db0[1] = cvt_tf32(pb[0].y);                 \
        db0[2] = cvt_tf32(pb[0].z); db0[3] = cvt_tf32(pb[0].w);                 \
        float* db1 = Bs[BUF] + b_row1 * BLD + b_c4 * 4;                         \
        db1[0] = cvt_tf32(pb[1].x); db1[1] = cvt_tf32(pb[1].y);                 \
        db1[2] = cvt_tf32(pb[1].z); db1[3] = cvt_tf32(pb[1].w);                 \
    } while (0)

    wmma::fragment<wmma::accumulator, 16, 16, 8, float> acc[4][2];
#pragma unroll
    for (int i = 0; i < 4; i++)
#pragma unroll
        for (int j = 0; j < 2; j++)
            wmma::fill_fragment(acc[i][j], 0.0f);

    G_LOAD(0);
    G_STS(0);
    __syncthreads();

    int buf = 0;
    for (int k0 = 0; k0 < CC; k0 += GBK, buf ^= 1) {
        if (k0 + GBK < CC) G_LOAD(k0 + GBK);

#pragma unroll
        for (int kk = 0; kk < GBK; kk += 8) {
            wmma::fragment<wmma::matrix_a, 16, 16, 8, wmma::precision::tf32, wmma::row_major> af[4];
            wmma::fragment<wmma::matrix_b, 16, 16, 8, wmma::precision::tf32, wmma::row_major> bf[2];
#pragma unroll
            for (int i = 0; i < 4; i++)
                wmma::load_matrix_sync(af[i], As[buf] + (warp_m * 64 + i * 16) * ALD + kk, ALD);
#pragma unroll
            for (int j = 0; j < 2; j++)
                wmma::load_matrix_sync(bf[j], Bs[buf] + kk * BLD + warp_n * 32 + j * 16, BLD);
#pragma unroll
            for (int i = 0; i < 4; i++)
#pragma unroll
                for (int j = 0; j < 2; j++)
                    wmma::mma_sync(acc[i][j], af[i], bf[j], acc[i][j]);
        }

        if (k0 + GBK < CC) G_STS(buf ^ 1);
        __syncthreads();
    }

    // epilogue
    float* st = stage + wid * 16 * 20;
#pragma unroll
    for (int i = 0; i < 4; i++) {
#pragma unroll
        for (int j = 0; j < 2; j++) {
            wmma::store_matrix_sync(st, acc[i][j], 20, wmma::mem_row_major);
            __syncwarp();
            int row0 = m0 + warp_m * 64 + i * 16;
            int col0 = n0 + warp_n * 32 + j * 16;
#pragma unroll
            for (int e = lane; e < 256; e += 32) {
                int r = e >> 4, c = e & 15;
                int m = row0 + r, n = col0 + c;
                float val = st[r * 20 + c] + bias[n];
                if (split) {
                    int b = m >> 11, t = m & 2047;
                    int h = n >> 6,  d = n & 63;
                    out[((((size_t)b * NH + h) * TT + t) << 6) + d] = val;
                } else {
                    out[(size_t)m * CC + n] = val;
                }
            }
            __syncwarp();
        }
    }
#undef G_LOAD
#undef G_STS
}

// ============================================================================
// Flash attention v2: register-resident FA2 with raw mma.m16n8k8.tf32.
// Block = 8 warps, Q tile 128 rows (16 rows/warp). K/V tiles 64, double-buffered.
// S, softmax state, O all in registers; only P round-trips (warp-private) smem.
// ============================================================================
#define KTILE 64
#define KLD 68
#define VLD 72
#define PLD 68
#define ATT_SMEM_FLOATS (2 * KTILE * KLD + 2 * KTILE * VLD + 8 * 16 * PLD)
#define ATT_SMEM_BYTES (ATT_SMEM_FLOATS * 4)

__device__ __forceinline__ void mma_tf32_16x8x8(
    float d[4], const uint32_t a[4], const uint32_t b0, const uint32_t b1)
{
    asm volatile(
        "mma.sync.aligned.m16n8k8.row.col.f32.tf32.tf32.f32 "
        "{%0,%1,%2,%3}, {%4,%5,%6,%7}, {%8,%9}, {%0,%1,%2,%3};\n"
        : "+f"(d[0]), "+f"(d[1]), "+f"(d[2]), "+f"(d[3])
        : "r"(a[0]), "r"(a[1]), "r"(a[2]), "r"(a[3]), "r"(b0), "r"(b1));
}

__global__ __launch_bounds__(256, 1) void attn_kernel(
    const float* __restrict__ q, const float* __restrict__ k,
    const float* __restrict__ v, float* __restrict__ y)
{
    extern __shared__ float sm[];
    float* Ks = sm;                              // 2 x 64 x KLD
    float* Vs = sm + 2 * KTILE * KLD;            // 2 x 64 x VLD
    float* Ps = sm + 2 * KTILE * KLD + 2 * KTILE * VLD;  // 8 warps x 16 x PLD

    const int qt = blockIdx.x;      // 0..15  (128-row q tiles)
    const int h  = blockIdx.y;
    const int b  = blockIdx.z;
    const int tid  = threadIdx.x;
    const int w    = tid >> 5;
    const int lane = tid & 31;
    const int grp  = lane >> 2;     // 0..7
    const int tg   = lane & 3;      // 0..3

    const size_t head_base = ((size_t)b * NH + h) * TT * HS;
    const float* qb  = q + head_base + (size_t)qt * 128 * HS;
    const float* kb0 = k + head_base;
    const float* vb0 = v + head_base;

    // ---- stage Q (scaled, tf32) into Ps, then pull Q fragments to registers
#pragma unroll
    for (int i = tid; i < 2048; i += 256) {
        int r = i >> 4, c4 = i & 15;
        float4 t4 = *(const float4*)(qb + r * HS + c4 * 4);
        float* dst = Ps + r * PLD + c4 * 4;
        dst[0] = cvt_tf32(t4.x * 0.125f); dst[1] = cvt_tf32(t4.y * 0.125f);
        dst[2] = cvt_tf32(t4.z * 0.125f); dst[3] = cvt_tf32(t4.w * 0.125f);
    }
    __syncthreads();

    float* Pw = Ps + w * 16 * PLD;   // this warp's 16 rows
    uint32_t qf[8][4];
#pragma unroll
    for (int ks = 0; ks < 8; ks++) {
        qf[ks][0] = __float_as_uint(Pw[grp * PLD + ks * 8 + tg]);
        qf[ks][1] = __float_as_uint(Pw[(grp + 8) * PLD + ks * 8 + tg]);
        qf[ks][2] = __float_as_uint(Pw[grp * PLD + ks * 8 + tg + 4]);
        qf[ks][3] = __float_as_uint(Pw[(grp + 8) * PLD + ks * 8 + tg + 4]);
    }
    __syncthreads();   // Ps free for P use

    float oacc[8][4];
#pragma unroll
    for (int j = 0; j < 8; j++)
#pragma unroll
        for (int c = 0; c < 4; c++) oacc[j][c] = 0.0f;

    float m0r = -1e30f, m1r = -1e30f, l0 = 0.0f, l1 = 0.0f;

    const int warp_row_base = qt * 128 + w * 16;
    const int row0 = warp_row_base + grp;
    const int row1 = row0 + 8;
    const int nk = 2 * qt + 2;

    // K/V gmem->reg prefetch staging
    float4 kreg[4], vreg[4];
#define KV_LOAD(KT_)                                                            \
    do {                                                                        \
        const float* kb = kb0 + (size_t)(KT_) * KTILE * HS;                     \
        const float* vb = vb0 + (size_t)(KT_) * KTILE * HS;                     \
        _Pragma("unroll")                                                       \
        for (int jj = 0; jj < 4; jj++) {                                        \
            int idx = tid + 256 * jj;                                           \
            int r = idx >> 4, c4 = idx & 15;                                    \
            kreg[jj] = *(const float4*)(kb + r * HS + c4 * 4);                  \
            vreg[jj] = *(const float4*)(vb + r * HS + c4 * 4);                  \
        }                                                                       \
    } while (0)

#define KV_STS(BUF)                                                             \
    do {                                                                        \
        float* kdst = Ks + (BUF) * KTILE * KLD;                                 \
        float* vdst = Vs + (BUF) * KTILE * VLD;                                 \
        _Pragma("unroll")                                                       \
        for (int jj = 0; jj < 4; jj++) {                                        \
            int idx = tid + 256 * jj;                                           \
            int r = idx >> 4, c4 = idx & 15;                                    \
            float* dk = kdst + r * KLD + c4 * 4;                                \
            dk[0] = cvt_tf32(kreg[jj].x); dk[1] = cvt_tf32(kreg[jj].y);         \
            dk[2] = cvt_tf32(kreg[jj].z); dk[3] = cvt_tf32(kreg[jj].w);         \
            float* dv = vdst + r * VLD + c4 * 4;                                \
            dv[0] = cvt_tf32(vreg[jj].x); dv[1] = cvt_tf32(vreg[jj].y);         \
            dv[2] = cvt_tf32(vreg[jj].z); dv[3] = cvt_tf32(vreg[jj].w);         \
        }                                                                       \
    } while (0)

    KV_LOAD(0);
    KV_STS(0);
    __syncthreads();

    for (int kt = 0; kt < nk; kt++) {
        const int buf = kt & 1;
        if (kt + 1 < nk) KV_LOAD(kt + 1);

        const float* Kb = Ks + buf * KTILE * KLD;
        const float* Vb = Vs + buf * KTILE * VLD;

        // warp-level causal skip: tile entirely above this warp's rows
        const bool active = (kt * KTILE) <= (warp_row_base + 15);
        if (active) {
            // ---- S = Q K^T (16 x 64 per warp), register accumulators
            float sacc[8][4];
#pragma unroll
            for (int j = 0; j < 8; j++)
#pragma unroll
                for (int c = 0; c < 4; c++) sacc[j][c] = 0.0f;

#pragma unroll
            for (int j = 0; j < 8; j++) {
#pragma unroll
                for (int ks = 0; ks < 8; ks++) {
                    uint32_t bb0 = __float_as_uint(Kb[(j * 8 + grp) * KLD + ks * 8 + tg]);
                    uint32_t bb1 = __float_as_uint(Kb[(j * 8 + grp) * KLD + ks * 8 + tg + 4]);
                    mma_tf32_16x8x8(sacc[j], qf[ks], bb0, bb1);
                }
            }

            // ---- causal mask (only when tile crosses the diagonal)
            if (kt * KTILE + KTILE - 1 > warp_row_base) {
#pragma unroll
                for (int j = 0; j < 8; j++) {
#pragma unroll
                    for (int c = 0; c < 2; c++) {
                        int col = kt * KTILE + j * 8 + 2 * tg + c;
                        if (col > row0) sacc[j][c]     = -1e30f;
                        if (col > row1) sacc[j][2 + c] = -1e30f;
                    }
                }
            }

            // ---- online softmax, all in registers
            float mx0 = -1e30f, mx1 = -1e30f;
#pragma unroll
            for (int j = 0; j < 8; j++) {
                mx0 = fmaxf(mx0, fmaxf(sacc[j][0], sacc[j][1]));
                mx1 = fmaxf(mx1, fmaxf(sacc[j][2], sacc[j][3]));
            }
            mx0 = fmaxf(mx0, __shfl_xor_sync(0xffffffffu, mx0, 1));
            mx0 = fmaxf(mx0, __shfl_xor_sync(0xffffffffu, mx0, 2));
            mx1 = fmaxf(mx1, __shfl_xor_sync(0xffffffffu, mx1, 1));
            mx1 = fmaxf(mx1, __shfl_xor_sync(0xffffffffu, mx1, 2));

            float mn0 = fmaxf(m0r, mx0), mn1 = fmaxf(m1r, mx1);
            float a0 = __expf(m0r - mn0), a1 = __expf(m1r - mn1);
            m0r = mn0; m1r = mn1;

            float s0 = 0.0f, s1 = 0.0f;
#pragma unroll
            for (int j = 0; j < 8; j++) {
                float p;
                p = __expf(sacc[j][0] - mn0); sacc[j][0] = p; s0 += p;
                p = __expf(sacc[j][1] - mn0); sacc[j][1] = p; s0 += p;
                p = __expf(sacc[j][2] - mn1); sacc[j][2] = p; s1 += p;
                p = __expf(sacc[j][3] - mn1); sacc[j][3] = p; s1 += p;
            }
            s0 += __shfl_xor_sync(0xffffffffu, s0, 1);
            s0 += __shfl_xor_sync(0xffffffffu, s0, 2);
            s1 += __shfl_xor_sync(0xffffffffu, s1, 1);
            s1 += __shfl_xor_sync(0xffffffffu, s1, 2);
            l0 = l0 * a0 + s0;
            l1 = l1 * a1 + s1;

            // rescale O registers
#pragma unroll
            for (int j = 0; j < 8; j++) {
                oacc[j][0] *= a0; oacc[j][1] *= a0;
                oacc[j][2] *= a1; oacc[j][3] *= a1;
            }

            // ---- stash P (tf32) in warp-private smem for A-fragment re-layout
#pragma unroll
            for (int j = 0; j < 8; j++) {
                float* p0 = Pw + grp * PLD + j * 8 + 2 * tg;
                p0[0] = cvt_tf32(sacc[j][0]); p0[1] = cvt_tf32(sacc[j][1]);
                float* p1 = Pw + (grp + 8) * PLD + j * 8 + 2 * tg;
                p1[0] = cvt_tf32(sacc[j][2]); p1[1] = cvt_tf32(sacc[j][3]);
            }
            __syncwarp();

            // ---- O += P V
#pragma unroll
            for (int ks = 0; ks < 8; ks++) {
                uint32_t pa[4];
                pa[0] = __float_as_uint(Pw[grp * PLD + ks * 8 + tg]);
                pa[1] = __float_as_uint(Pw[(grp + 8) * PLD + ks * 8 + tg]);
                pa[2] = __float_as_uint(Pw[grp * PLD + ks * 8 + tg + 4]);
                pa[3] = __float_as_uint(Pw[(grp + 8) * PLD + ks * 8 + tg + 4]);
#pragma unroll
                for (int j = 0; j < 8; j++) {
                    uint32_t vb0f = __float_as_uint(Vb[(ks * 8 + tg) * VLD + j * 8 + grp]);
                    uint32_t vb1f = __float_as_uint(Vb[(ks * 8 + tg + 4) * VLD + j * 8 + grp]);
                    mma_tf32_16x8x8(oacc[j], pa, vb0f, vb1f);
                }
            }
            __syncwarp();
        }

        if (kt + 1 < nk) KV_STS(buf ^ 1);
        __syncthreads();
    }

    // ---- normalize and write out via warp-private smem (coalesced)
    float inv0 = 1.0f / l0, inv1 = 1.0f / l1;
#pragma unroll
    for (int j = 0; j < 8; j++) {
        float* p0 = Pw + grp * PLD + j * 8 + 2 * tg;
        p0[0] = oacc[j][0] * inv0; p0[1] = oacc[j][1] * inv0;
        float* p1 = Pw + (grp + 8) * PLD + j * 8 + 2 * tg;
        p1[0] = oacc[j][2] * inv1; p1[1] = oacc[j][3] * inv1;
    }
    __syncwarp();

    float* yb = y + ((size_t)b * TT + qt * 128 + w * 16) * CC + h * HS;
#pragma unroll
    for (int i = lane; i < 256; i += 32) {   // 16 rows x 16 float4
        int r = i >> 4, c4 = i & 15;
        float4 val = *(const float4*)(Pw + r * PLD + c4 * 4);
        *(float4*)(yb + (size_t)r * CC + c4 * 4) = val;
    }
#undef KV_LOAD
#undef KV_STS
}

// ============================================================================
// launch
// ============================================================================
extern "C" void kernel_launch(void* const* d_in, const int* in_sizes, int n_in,
                              void* d_out, int out_size)
{
    const float* x  = (const float*)d_in[0];
    const float* Wk = (const float*)d_in[1];
    const float* bk = (const float*)d_in[2];
    const float* Wq = (const float*)d_in[3];
    const float* bq = (const float*)d_in[4];
    const float* Wv = (const float*)d_in[5];
    const float* bv = (const float*)d_in[6];
    const float* Wo = (const float*)d_in[7];
    const float* bo = (const float*)d_in[8];
    float* out = (float*)d_out;

    float *qp, *kp, *vp, *yp;
    cudaGetSymbolAddress((void**)&qp, g_q);
    cudaGetSymbolAddress((void**)&kp, g_k);
    cudaGetSymbolAddress((void**)&vp, g_v);
    cudaGetSymbolAddress((void**)&yp, g_y);

    cudaFuncSetAttribute(attn_kernel, cudaFuncAttributeMaxDynamicSharedMemorySize,
                         ATT_SMEM_BYTES);

    dim3 ggrid(CC / 128, (BB * TT) / 128);
    gemm_tf32_kernel<<<ggrid, 256>>>(x, Wq, bq, qp, 1);
    gemm_tf32_kernel<<<ggrid, 256>>>(x, Wk, bk, kp, 1);
    gemm_tf32_kernel<<<ggrid, 256>>>(x, Wv, bv, vp, 1);

    dim3 agrid(TT / 128, NH, BB);
    attn_kernel<<<agrid, 256, ATT_SMEM_BYTES>>>(qp, kp, vp, yp);

    gemm_tf32_kernel<<<ggrid, 256>>>(yp, Wo, bo, out, 0);
}

// round 3
// speedup vs baseline: 1.7387x; 1.1107x over previous
#include <cuda_runtime.h>
#include <mma.h>
#include <cstdint>

using namespace nvcuda;

#define BB 4
#define TT 2048
#define CC 1024
#define NH 16
#define HS 64

// ---------------- scratch (allocation-free: __device__ globals) -------------
__device__ float g_q[BB * TT * CC];    // (B,H,T,D) tf32-rounded, pre-scaled
__device__ float g_k[BB * TT * CC];    // (B,H,T,D) tf32-rounded
__device__ float g_v[BB * TT * CC];    // (B,H,T,D) tf32-rounded
__device__ float g_y[BB * TT * CC];    // (B,T,C)  tf32-rounded
__device__ float g_xc[BB * TT * CC];   // x tf32-rounded
__device__ float g_wq[CC * CC];
__device__ float g_wk[CC * CC];
__device__ float g_wv[CC * CC];
__device__ float g_wo[CC * CC];

__device__ __forceinline__ float cvt_tf32(float x) {
    return wmma::__float_to_tf32(x);
}

__device__ __forceinline__ void cp16(uint32_t dst, const float* src) {
    asm volatile("cp.async.cg.shared.global [%0], [%1], 16;\n" :: "r"(dst), "l"(src));
}
#define CP_COMMIT() asm volatile("cp.async.commit_group;\n" ::: "memory")
#define CP_WAIT(N)  asm volatile("cp.async.wait_group %0;\n" :: "n"(N) : "memory")

__device__ __forceinline__ void mma_tf32_16x8x8(
    float d[4], const uint32_t a[4], const uint32_t b0, const uint32_t b1)
{
    asm volatile(
        "mma.sync.aligned.m16n8k8.row.col.f32.tf32.tf32.f32 "
        "{%0,%1,%2,%3}, {%4,%5,%6,%7}, {%8,%9}, {%0,%1,%2,%3};\n"
        : "+f"(d[0]), "+f"(d[1]), "+f"(d[2]), "+f"(d[3])
        : "r"(a[0]), "r"(a[1]), "r"(a[2]), "r"(a[3]), "r"(b0), "r"(b1));
}

// ============================================================================
// prep: round fp32 -> tf32 (RN), vectorized
// ============================================================================
__global__ void round_kernel(const float* __restrict__ in, float* __restrict__ out, int n4)
{
    int i = blockIdx.x * blockDim.x + threadIdx.x;
    if (i < n4) {
        float4 v = ((const float4*)in)[i];
        v.x = cvt_tf32(v.x); v.y = cvt_tf32(v.y);
        v.z = cvt_tf32(v.z); v.w = cvt_tf32(v.w);
        ((float4*)out)[i] = v;
    }
}

// ============================================================================
// GEMM: out[8192,1024] = A @ W + bias. A,W pre-rounded tf32.
// CTA 128x128, 4 warps (warp tile 64x64), BK=32, 3-stage cp.async pipeline.
// mode 0: plain fp32 row-major (final output). mode 1: tf32-round(val*scale),
// scatter to (B,H,T,D).
// ============================================================================
#define G_ALD 36
#define G_BLD 132
#define G_NST 3
#define GEMM_SMEM ((G_NST * 128 * G_ALD + G_NST * 32 * G_BLD) * 4)

__global__ __launch_bounds__(128, 2) void gemm_tf32_kernel(
    const float* __restrict__ A, const float* __restrict__ W,
    const float* __restrict__ bias, float* __restrict__ out,
    int mode, float scale)
{
    extern __shared__ float sm[];
    float* As = sm;                          // 3 x 128 x 36
    float* Bs = sm + G_NST * 128 * G_ALD;    // 3 x 32 x 132

    const int tid  = threadIdx.x;
    const int wid  = tid >> 5;
    const int lane = tid & 31;
    const int grp  = lane >> 2;
    const int tg   = lane & 3;

    const int m0 = blockIdx.y * 128;
    const int n0 = blockIdx.x * 128;
    const int warp_m = wid >> 1;
    const int warp_n = wid & 1;

    const uint32_t as_addr = (uint32_t)__cvta_generic_to_shared(As);
    const uint32_t bs_addr = (uint32_t)__cvta_generic_to_shared(Bs);

    const int a_r = tid >> 3, a_k = tid & 7;    // A: 8 chunks/row, 16 rows per c
    const int b_r = tid >> 5, b_n = tid & 31;   // B: 32 chunks/row, 4 rows per c

#define GEMM_ISSUE(BUF, K0)                                                     \
    do {                                                                        \
        uint32_t sa = as_addr + (uint32_t)(BUF) * 128 * G_ALD * 4;              \
        uint32_t sb = bs_addr + (uint32_t)(BUF) * 32 * G_BLD * 4;               \
        _Pragma("unroll")                                                       \
        for (int c = 0; c < 8; c++) {                                           \
            int row = c * 16 + a_r;                                             \
            cp16(sa + (row * G_ALD + a_k * 4) * 4,                              \
                 A + (size_t)(m0 + row) * CC + (K0) + a_k * 4);                 \
        }                                                                       \
        _Pragma("unroll")                                                       \
        for (int c = 0; c < 8; c++) {                                           \
            int row = c * 4 + b_r;                                              \
            cp16(sb + (row * G_BLD + b_n * 4) * 4,                              \
                 W + (size_t)((K0) + row) * CC + n0 + b_n * 4);                 \
        }                                                                       \
    } while (0)

    float acc[4][8][4];
#pragma unroll
    for (int i = 0; i < 4; i++)
#pragma unroll
        for (int j = 0; j < 8; j++)
#pragma unroll
            for (int c = 0; c < 4; c++) acc[i][j][c] = 0.0f;

    GEMM_ISSUE(0, 0);  CP_COMMIT();
    GEMM_ISSUE(1, 32); CP_COMMIT();
    CP_WAIT(1);
    __syncthreads();

    int buf = 0;
#pragma unroll 1
    for (int s = 0; s < 32; s++) {
        if (s + 2 < 32) { GEMM_ISSUE((s + 2) % G_NST, (s + 2) * 32); }
        CP_COMMIT();

        const float* Ab = As + buf * 128 * G_ALD;
        const float* Bb = Bs + buf * 32 * G_BLD;

#pragma unroll
        for (int kk = 0; kk < 4; kk++) {
            uint32_t af[4][4];
            uint32_t bf[8][2];
#pragma unroll
            for (int i = 0; i < 4; i++) {
                int rb = warp_m * 64 + i * 16;
                af[i][0] = __float_as_uint(Ab[(rb + grp)     * G_ALD + kk * 8 + tg]);
                af[i][1] = __float_as_uint(Ab[(rb + grp + 8) * G_ALD + kk * 8 + tg]);
                af[i][2] = __float_as_uint(Ab[(rb + grp)     * G_ALD + kk * 8 + tg + 4]);
                af[i][3] = __float_as_uint(Ab[(rb + grp + 8) * G_ALD + kk * 8 + tg + 4]);
            }
#pragma unroll
            for (int j = 0; j < 8; j++) {
                int cb = warp_n * 64 + j * 8 + grp;
                bf[j][0] = __float_as_uint(Bb[(kk * 8 + tg)     * G_BLD + cb]);
                bf[j][1] = __float_as_uint(Bb[(kk * 8 + tg + 4) * G_BLD + cb]);
            }
#pragma unroll
            for (int i = 0; i < 4; i++)
#pragma unroll
                for (int j = 0; j < 8; j++)
                    mma_tf32_16x8x8(acc[i][j], af[i], bf[j][0], bf[j][1]);
        }

        CP_WAIT(1);
        __syncthreads();
        buf++; if (buf == G_NST) buf = 0;
    }

    // ---- epilogue
    float2 bj[8];
#pragma unroll
    for (int j = 0; j < 8; j++)
        bj[j] = *(const float2*)(bias + n0 + warp_n * 64 + j * 8 + tg * 2);

#pragma unroll
    for (int i = 0; i < 4; i++) {
        int r0 = m0 + warp_m * 64 + i * 16 + grp;
#pragma unroll
        for (int j = 0; j < 8; j++) {
            int n = n0 + warp_n * 64 + j * 8 + tg * 2;
            float v00 = acc[i][j][0] + bj[j].x;
            float v01 = acc[i][j][1] + bj[j].y;
            float v10 = acc[i][j][2] + bj[j].x;
            float v11 = acc[i][j][3] + bj[j].y;
            if (mode == 0) {
                *(float2*)(out + (size_t)r0 * CC + n)       = make_float2(v00, v01);
                *(float2*)(out + (size_t)(r0 + 8) * CC + n) = make_float2(v10, v11);
            } else {
                int b = r0 >> 11, t = r0 & 2047;
                int h = n >> 6,  d = n & 63;
                size_t addr = ((((size_t)b * NH + h) * TT + t) << 6) + d;
                *(float2*)(out + addr) =
                    make_float2(cvt_tf32(v00 * scale), cvt_tf32(v01 * scale));
                *(float2*)(out + addr + 8 * 64) =
                    make_float2(cvt_tf32(v10 * scale), cvt_tf32(v11 * scale));
            }
        }
    }
#undef GEMM_ISSUE
}

// ============================================================================
// Flash attention: register-resident FA2, cp.async double-buffered K/V.
// Block = 8 warps, Q tile 128 rows (16/warp). K/V tiles 64. Inputs pre-rounded
// tf32; Q pre-scaled. Output y written tf32-rounded.
// ============================================================================
#define KLD 68
#define VLD 72
#define PLD 68
#define ATT_SMEM ((2 * 64 * KLD + 2 * 64 * VLD + 128 * PLD) * 4)

__global__ __launch_bounds__(256, 1) void attn_kernel(
    const float* __restrict__ q, const float* __restrict__ k,
    const float* __restrict__ v, float* __restrict__ y)
{
    extern __shared__ float sm[];
    float* Ks = sm;                       // 2 x 64 x KLD
    float* Vs = sm + 2 * 64 * KLD;        // 2 x 64 x VLD
    float* Ps = sm + 2 * 64 * KLD + 2 * 64 * VLD;  // 128 x PLD

    const int qt = (gridDim.x - 1) - blockIdx.x;   // long tiles first
    const int h  = blockIdx.y;
    const int b  = blockIdx.z;
    const int tid  = threadIdx.x;
    const int w    = tid >> 5;
    const int lane = tid & 31;
    const int grp  = lane >> 2;
    const int tg   = lane & 3;

    const size_t head_base = ((size_t)b * NH + h) * TT * HS;
    const float* qb  = q + head_base + (size_t)qt * 128 * HS;
    const float* kb0 = k + head_base;
    const float* vb0 = v + head_base;

    const uint32_t ks_addr = (uint32_t)__cvta_generic_to_shared(Ks);
    const uint32_t vs_addr = (uint32_t)__cvta_generic_to_shared(Vs);

#define KV_ISSUE(KT_, BUF_)                                                     \
    do {                                                                        \
        const float* kb = kb0 + (size_t)(KT_) * 64 * HS;                        \
        const float* vb = vb0 + (size_t)(KT_) * 64 * HS;                        \
        uint32_t kbase = ks_addr + (uint32_t)(BUF_) * 64 * KLD * 4;             \
        uint32_t vbase = vs_addr + (uint32_t)(BUF_) * 64 * VLD * 4;             \
        _Pragma("unroll")                                                       \
        for (int c = 0; c < 4; c++) {                                           \
            int g2 = c * 256 + tid;                                             \
            int row = g2 >> 4, kc = g2 & 15;                                    \
            cp16(kbase + (row * KLD + kc * 4) * 4, kb + row * HS + kc * 4);     \
            cp16(vbase + (row * VLD + kc * 4) * 4, vb + row * HS + kc * 4);     \
        }                                                                       \
    } while (0)

    const int nk = 2 * qt + 2;

    // start first K/V load immediately, overlap with Q staging
    KV_ISSUE(0, 0);
    CP_COMMIT();

    // stage Q into Ps (pre-rounded, pre-scaled), pull fragments to registers
#pragma unroll
    for (int i = tid; i < 2048; i += 256) {
        int r = i >> 4, c4 = i & 15;
        *(float4*)(Ps + r * PLD + c4 * 4) = *(const float4*)(qb + r * HS + c4 * 4);
    }
    __syncthreads();

    float* Pw = Ps + w * 16 * PLD;
    uint32_t qf[8][4];
#pragma unroll
    for (int ks = 0; ks < 8; ks++) {
        qf[ks][0] = __float_as_uint(Pw[grp * PLD + ks * 8 + tg]);
        qf[ks][1] = __float_as_uint(Pw[(grp + 8) * PLD + ks * 8 + tg]);
        qf[ks][2] = __float_as_uint(Pw[grp * PLD + ks * 8 + tg + 4]);
        qf[ks][3] = __float_as_uint(Pw[(grp + 8) * PLD + ks * 8 + tg + 4]);
    }

    float oacc[8][4];
#pragma unroll
    for (int j = 0; j < 8; j++)
#pragma unroll
        for (int c = 0; c < 4; c++) oacc[j][c] = 0.0f;

    float m0r = -1e30f, m1r = -1e30f, l0 = 0.0f, l1 = 0.0f;

    const int warp_row_base = qt * 128 + w * 16;
    const int row0 = warp_row_base + grp;
    const int row1 = row0 + 8;

    CP_WAIT(0);
    __syncthreads();

#pragma unroll 1
    for (int kt = 0; kt < nk; kt++) {
        const int buf = kt & 1;
        if (kt + 1 < nk) { KV_ISSUE(kt + 1, buf ^ 1); CP_COMMIT(); }

        const float* Kb = Ks + buf * 64 * KLD;
        const float* Vb = Vs + buf * 64 * VLD;

        const bool active = (kt * 64) <= (warp_row_base + 15);
        if (active) {
            // ---- S = Q K^T
            float sacc[8][4];
#pragma unroll
            for (int j = 0; j < 8; j++)
#pragma unroll
                for (int c = 0; c < 4; c++) sacc[j][c] = 0.0f;

#pragma unroll
            for (int j = 0; j < 8; j++) {
#pragma unroll
                for (int ks = 0; ks < 8; ks++) {
                    uint32_t bb0 = __float_as_uint(Kb[(j * 8 + grp) * KLD + ks * 8 + tg]);
                    uint32_t bb1 = __float_as_uint(Kb[(j * 8 + grp) * KLD + ks * 8 + tg + 4]);
                    mma_tf32_16x8x8(sacc[j], qf[ks], bb0, bb1);
                }
            }

            // ---- causal mask
            if (kt * 64 + 63 > warp_row_base) {
#pragma unroll
                for (int j = 0; j < 8; j++) {
#pragma unroll
                    for (int c = 0; c < 2; c++) {
                        int col = kt * 64 + j * 8 + 2 * tg + c;
                        if (col > row0) sacc[j][c]     = -1e30f;
                        if (col > row1) sacc[j][2 + c] = -1e30f;
                    }
                }
            }

            // ---- online softmax (registers)
            float mx0 = -1e30f, mx1 = -1e30f;
#pragma unroll
            for (int j = 0; j < 8; j++) {
                mx0 = fmaxf(mx0, fmaxf(sacc[j][0], sacc[j][1]));
                mx1 = fmaxf(mx1, fmaxf(sacc[j][2], sacc[j][3]));
            }
            mx0 = fmaxf(mx0, __shfl_xor_sync(0xffffffffu, mx0, 1));
            mx0 = fmaxf(mx0, __shfl_xor_sync(0xffffffffu, mx0, 2));
            mx1 = fmaxf(mx1, __shfl_xor_sync(0xffffffffu, mx1, 1));
            mx1 = fmaxf(mx1, __shfl_xor_sync(0xffffffffu, mx1, 2));

            float mn0 = fmaxf(m0r, mx0), mn1 = fmaxf(m1r, mx1);
            float a0 = __expf(m0r - mn0), a1 = __expf(m1r - mn1);
            m0r = mn0; m1r = mn1;

            float s0 = 0.0f, s1 = 0.0f;
#pragma unroll
            for (int j = 0; j < 8; j++) {
                float p;
                p = __expf(sacc[j][0] - mn0); sacc[j][0] = p; s0 += p;
                p = __expf(sacc[j][1] - mn0); sacc[j][1] = p; s0 += p;
                p = __expf(sacc[j][2] - mn1); sacc[j][2] = p; s1 += p;
                p = __expf(sacc[j][3] - mn1); sacc[j][3] = p; s1 += p;
            }
            s0 += __shfl_xor_sync(0xffffffffu, s0, 1);
            s0 += __shfl_xor_sync(0xffffffffu, s0, 2);
            s1 += __shfl_xor_sync(0xffffffffu, s1, 1);
            s1 += __shfl_xor_sync(0xffffffffu, s1, 2);
            l0 = l0 * a0 + s0;
            l1 = l1 * a1 + s1;

#pragma unroll
            for (int j = 0; j < 8; j++) {
                oacc[j][0] *= a0; oacc[j][1] *= a0;
                oacc[j][2] *= a1; oacc[j][3] *= a1;
            }

            // ---- stash P (tf32) in warp-private smem
#pragma unroll
            for (int j = 0; j < 8; j++) {
                float* p0 = Pw + grp * PLD + j * 8 + 2 * tg;
                p0[0] = cvt_tf32(sacc[j][0]); p0[1] = cvt_tf32(sacc[j][1]);
                float* p1 = Pw + (grp + 8) * PLD + j * 8 + 2 * tg;
                p1[0] = cvt_tf32(sacc[j][2]); p1[1] = cvt_tf32(sacc[j][3]);
            }
            __syncwarp();

            // ---- O += P V
#pragma unroll
            for (int ks = 0; ks < 8; ks++) {
                uint32_t pa[4];
                pa[0] = __float_as_uint(Pw[grp * PLD + ks * 8 + tg]);
                pa[1] = __float_as_uint(Pw[(grp + 8) * PLD + ks * 8 + tg]);
                pa[2] = __float_as_uint(Pw[grp * PLD + ks * 8 + tg + 4]);
                pa[3] = __float_as_uint(Pw[(grp + 8) * PLD + ks * 8 + tg + 4]);
#pragma unroll
                for (int j = 0; j < 8; j++) {
                    uint32_t vb0f = __float_as_uint(Vb[(ks * 8 + tg) * VLD + j * 8 + grp]);
                    uint32_t vb1f = __float_as_uint(Vb[(ks * 8 + tg + 4) * VLD + j * 8 + grp]);
                    mma_tf32_16x8x8(oacc[j], pa, vb0f, vb1f);
                }
            }
            __syncwarp();
        }

        if (kt + 1 < nk) CP_WAIT(0);
        __syncthreads();
    }

    // ---- normalize, round to tf32, write y (B,T,C)
    float inv0 = 1.0f / l0, inv1 = 1.0f / l1;
#pragma unroll
    for (int j = 0; j < 8; j++) {
        float* p0 = Pw + grp * PLD + j * 8 + 2 * tg;
        p0[0] = cvt_tf32(oacc[j][0] * inv0); p0[1] = cvt_tf32(oacc[j][1] * inv0);
        float* p1 = Pw + (grp + 8) * PLD + j * 8 + 2 * tg;
        p1[0] = cvt_tf32(oacc[j][2] * inv1); p1[1] = cvt_tf32(oacc[j][3] * inv1);
    }
    __syncwarp();

    float* yb = y + ((size_t)b * TT + qt * 128 + w * 16) * CC + h * HS;
#pragma unroll
    for (int i = lane; i < 256; i += 32) {
        int r = i >> 4, c4 = i & 15;
        *(float4*)(yb + (size_t)r * CC + c4 * 4) = *(const float4*)(Pw + r * PLD + c4 * 4);
    }
#undef KV_ISSUE
}

// ============================================================================
// launch
// ============================================================================
extern "C" void kernel_launch(void* const* d_in, const int* in_sizes, int n_in,
                              void* d_out, int out_size)
{
    const float* x  = (const float*)d_in[0];
    const float* Wk = (const float*)d_in[1];
    const float* bk = (const float*)d_in[2];
    const float* Wq = (const float*)d_in[3];
    const float* bq = (const float*)d_in[4];
    const float* Wv = (const float*)d_in[5];
    const float* bv = (const float*)d_in[6];
    const float* Wo = (const float*)d_in[7];
    const float* bo = (const float*)d_in[8];
    float* out = (float*)d_out;

    float *qp, *kp, *vp, *yp, *xc, *wq, *wk, *wv, *wo;
    cudaGetSymbolAddress((void**)&qp, g_q);
    cudaGetSymbolAddress((void**)&kp, g_k);
    cudaGetSymbolAddress((void**)&vp, g_v);
    cudaGetSymbolAddress((void**)&yp, g_y);
    cudaGetSymbolAddress((void**)&xc, g_xc);
    cudaGetSymbolAddress((void**)&wq, g_wq);
    cudaGetSymbolAddress((void**)&wk, g_wk);
    cudaGetSymbolAddress((void**)&wv, g_wv);
    cudaGetSymbolAddress((void**)&wo, g_wo);

    cudaFuncSetAttribute(gemm_tf32_kernel,
                         cudaFuncAttributeMaxDynamicSharedMemorySize, GEMM_SMEM);
    cudaFuncSetAttribute(attn_kernel,
                         cudaFuncAttributeMaxDynamicSharedMemorySize, ATT_SMEM);

    // prep: tf32-round x and weights
    int nx4 = (BB * TT * CC) / 4, nw4 = (CC * CC) / 4;
    round_kernel<<<nx4 / 256, 256>>>(x,  xc, nx4);
    round_kernel<<<nw4 / 256, 256>>>(Wq, wq, nw4);
    round_kernel<<<nw4 / 256, 256>>>(Wk, wk, nw4);
    round_kernel<<<nw4 / 256, 256>>>(Wv, wv, nw4);
    round_kernel<<<nw4 / 256, 256>>>(Wo, wo, nw4);

    dim3 ggrid(CC / 128, (BB * TT) / 128);
    gemm_tf32_kernel<<<ggrid, 128, GEMM_SMEM>>>(xc, wq, bq, qp, 1, 0.125f);
    gemm_tf32_kernel<<<ggrid, 128, GEMM_SMEM>>>(xc, wk, bk, kp, 1, 1.0f);
    gemm_tf32_kernel<<<ggrid, 128, GEMM_SMEM>>>(xc, wv, bv, vp, 1, 1.0f);

    dim3 agrid(TT / 128, NH, BB);
    attn_kernel<<<agrid, 256, ATT_SMEM>>>(qp, kp, vp, yp);

    gemm_tf32_kernel<<<ggrid, 128, GEMM_SMEM>>>(yp, wo, bo, out, 0, 1.0f);
}

// round 9
// speedup vs baseline: 4.5450x; 2.6140x over previous
#include <cuda_runtime.h>
#include <cuda_fp16.h>
#include <cstdint>

#define BB 4
#define TT 2048
#define CC 1024
#define NH 16
#define HS 64

// ---------------- scratch (allocation-free: __device__ globals) -------------
__device__ __half g_q[BB * TT * CC];    // (B,H,T,D) fp16, pre-scaled by 0.125
__device__ __half g_k[BB * TT * CC];    // (B,H,T,D) fp16
__device__ __half g_v[BB * TT * CC];    // (B,H,D,T) fp16  (TRANSPOSED)
__device__ __half g_y[BB * TT * CC];    // (B,T,C)  fp16
__device__ __half g_xc[BB * TT * CC];   // x fp16
__device__ __half g_wq[CC * CC];        // W^T fp16 [n][k]
__device__ __half g_wk[CC * CC];
__device__ __half g_wv[CC * CC];
__device__ __half g_wo[CC * CC];

__device__ __forceinline__ void cp16(uint32_t dst, const void* src) {
    asm volatile("cp.async.cg.shared.global [%0], [%1], 16;\n" :: "r"(dst), "l"(src));
}
#define CP_COMMIT() asm volatile("cp.async.commit_group;\n" ::: "memory")
#define CP_WAIT(N)  asm volatile("cp.async.wait_group %0;\n" :: "n"(N) : "memory")

__device__ __forceinline__ void mma_f16(
    float d[4], const uint32_t a[4], uint32_t b0, uint32_t b1)
{
    asm volatile(
        "mma.sync.aligned.m16n8k16.row.col.f32.f16.f16.f32 "
        "{%0,%1,%2,%3}, {%4,%5,%6,%7}, {%8,%9}, {%0,%1,%2,%3};\n"
        : "+f"(d[0]), "+f"(d[1]), "+f"(d[2]), "+f"(d[3])
        : "r"(a[0]), "r"(a[1]), "r"(a[2]), "r"(a[3]), "r"(b0), "r"(b1));
}

__device__ __forceinline__ uint32_t pack_h2(float lo, float hi) {
    __half2 h = __floats2half2_rn(lo, hi);
    return *(uint32_t*)&h;
}

// ============================================================================
// prep: fp32 -> fp16
// ============================================================================
__global__ void round_half_kernel(const float* __restrict__ in,
                                  __half* __restrict__ out, int n4)
{
    int i = blockIdx.x * blockDim.x + threadIdx.x;
    if (i < n4) {
        float4 v = ((const float4*)in)[i];
        __half2* o = (__half2*)(out + (size_t)i * 4);
        o[0] = __floats2half2_rn(v.x, v.y);
        o[1] = __floats2half2_rn(v.z, v.w);
    }
}

// prep: W [k][n] fp32 -> W^T [n][k] fp16 (tiled transpose)
__global__ void transpose_w_kernel(const float* __restrict__ in,
                                   __half* __restrict__ out)
{
    __shared__ float t[32][33];
    int bx = blockIdx.x * 32, by = blockIdx.y * 32;
#pragma unroll
    for (int i = 0; i < 32; i += 8)
        t[threadIdx.y + i][threadIdx.x] = in[(size_t)(by + threadIdx.y + i) * CC + bx + threadIdx.x];
    __syncthreads();
#pragma unroll
    for (int i = 0; i < 32; i += 8)
        out[(size_t)(bx + threadIdx.y + i) * CC + by + threadIdx.x] =
            __float2half_rn(t[threadIdx.x][threadIdx.y + i]);
}

// ============================================================================
// GEMM: [8192,1024] = A(half) @ W^T(half,[n][k]) + bias, fp32 accum.
// CTA 128x128, 4 warps (warp 64x64), BK=32, 3-stage cp.async.
// mode 0: fp32 row-major out. mode 1: half (B,H,T,D), *scale. mode 2: half
// (B,H,D,T) transposed via smem-staged warp transpose.
// ============================================================================
#define G_LD 40
#define G_NST 3
#define G_STAGE (128 * G_LD)
#define GEMM_SMEM (G_NST * 2 * G_STAGE * 2)

__global__ __launch_bounds__(128, 2) void gemm_f16_kernel(
    const __half* __restrict__ A, const __half* __restrict__ Wt,
    const float* __restrict__ bias, void* __restrict__ outp,
    int mode, float scale)
{
    extern __shared__ __half smh[];
    __half* As = smh;
    __half* Bs = smh + G_NST * G_STAGE;

    const int tid  = threadIdx.x;
    const int wid  = tid >> 5;
    const int lane = tid & 31;
    const int grp  = lane >> 2;
    const int tg   = lane & 3;

    const int m0 = blockIdx.y * 128;
    const int n0 = blockIdx.x * 128;
    const int warp_m = wid >> 1;
    const int warp_n = wid & 1;

    const uint32_t as_addr = (uint32_t)__cvta_generic_to_shared(As);
    const uint32_t bs_addr = (uint32_t)__cvta_generic_to_shared(Bs);

#define GEMM_ISSUE(BUF, K0)                                                     \
    do {                                                                        \
        uint32_t sa = as_addr + (uint32_t)(BUF) * G_STAGE * 2;                  \
        uint32_t sb = bs_addr + (uint32_t)(BUF) * G_STAGE * 2;                  \
        _Pragma("unroll")                                                       \
        for (int c = 0; c < 4; c++) {                                           \
            int id = c * 128 + tid;                                             \
            int row = id >> 2, kc = id & 3;                                     \
            cp16(sa + (row * G_LD + kc * 8) * 2,                                \
                 A  + (size_t)(m0 + row) * CC + (K0) + kc * 8);                 \
            cp16(sb + (row * G_LD + kc * 8) * 2,                                \
                 Wt + (size_t)(n0 + row) * CC + (K0) + kc * 8);                 \
        }                                                                       \
    } while (0)

    float acc[4][8][4];
#pragma unroll
    for (int i = 0; i < 4; i++)
#pragma unroll
        for (int j = 0; j < 8; j++)
#pragma unroll
            for (int c = 0; c < 4; c++) acc[i][j][c] = 0.0f;

    GEMM_ISSUE(0, 0);  CP_COMMIT();
    GEMM_ISSUE(1, 32); CP_COMMIT();
    CP_WAIT(1);
    __syncthreads();

    int buf = 0;
#pragma unroll 1
    for (int s = 0; s < 32; s++) {
        if (s + 2 < 32) { GEMM_ISSUE((s + 2) % G_NST, (s + 2) * 32); }
        CP_COMMIT();

        const __half* Ab = As + buf * G_STAGE;
        const __half* Bb = Bs + buf * G_STAGE;

#pragma unroll
        for (int kk = 0; kk < 2; kk++) {
            uint32_t af[4][4];
            uint32_t bf[8][2];
#pragma unroll
            for (int i = 0; i < 4; i++) {
                int rb = warp_m * 64 + i * 16;
                af[i][0] = *(const uint32_t*)(Ab + (rb + grp)     * G_LD + kk * 16 + 2 * tg);
                af[i][1] = *(const uint32_t*)(Ab + (rb + grp + 8) * G_LD + kk * 16 + 2 * tg);
                af[i][2] = *(const uint32_t*)(Ab + (rb + grp)     * G_LD + kk * 16 + 2 * tg + 8);
                af[i][3] = *(const uint32_t*)(Ab + (rb + grp + 8) * G_LD + kk * 16 + 2 * tg + 8);
            }
#pragma unroll
            for (int j = 0; j < 8; j++) {
                int cb = warp_n * 64 + j * 8 + grp;
                bf[j][0] = *(const uint32_t*)(Bb + cb * G_LD + kk * 16 + 2 * tg);
                bf[j][1] = *(const uint32_t*)(Bb + cb * G_LD + kk * 16 + 2 * tg + 8);
            }
#pragma unroll
            for (int i = 0; i < 4; i++)
#pragma unroll
                for (int j = 0; j < 8; j++)
                    mma_f16(acc[i][j], af[i], bf[j][0], bf[j][1]);
        }

        CP_WAIT(1);
        __syncthreads();
        buf++; if (buf == G_NST) buf = 0;
    }

    // ---- epilogue
    float2 bj[8];
#pragma unroll
    for (int j = 0; j < 8; j++)
        bj[j] = *(const float2*)(bias + n0 + warp_n * 64 + j * 8 + tg * 2);

    if (mode == 2) {
        // V: warp transpose 64x64 through smem, write (B,H,D,T)
        __half* Ts = smh + wid * (64 * 72);
#pragma unroll
        for (int i = 0; i < 4; i++) {
            int r = i * 16 + grp;
#pragma unroll
            for (int j = 0; j < 8; j++) {
                int c = j * 8 + 2 * tg;
                Ts[c * 72 + r]           = __float2half_rn(acc[i][j][0] + bj[j].x);
                Ts[(c + 1) * 72 + r]     = __float2half_rn(acc[i][j][1] + bj[j].y);
                Ts[c * 72 + r + 8]       = __float2half_rn(acc[i][j][2] + bj[j].x);
                Ts[(c + 1) * 72 + r + 8] = __float2half_rn(acc[i][j][3] + bj[j].y);
            }
        }
        __syncwarp();
        __half* vout = (__half*)outp;
        const int b = m0 >> 11;
        const int h = (n0 + warp_n * 64) >> 6;
        const int t0 = (m0 & 2047) + warp_m * 64;   // batch-local token (FIXED)
#pragma unroll
        for (int idx = lane; idx < 512; idx += 32) {
            int c = idx >> 3, f = idx & 7;
            float4 val = *(const float4*)(Ts + c * 72 + f * 8);
            *(float4*)(vout + ((size_t)(b * NH + h) * HS + c) * TT + t0 + f * 8) = val;
        }
    } else {
#pragma unroll
        for (int i = 0; i < 4; i++) {
            int r0 = m0 + warp_m * 64 + i * 16 + grp;
#pragma unroll
            for (int j = 0; j < 8; j++) {
                int n = n0 + warp_n * 64 + j * 8 + tg * 2;
                float v00 = acc[i][j][0] + bj[j].x;
                float v01 = acc[i][j][1] + bj[j].y;
                float v10 = acc[i][j][2] + bj[j].x;
                float v11 = acc[i][j][3] + bj[j].y;
                if (mode == 0) {
                    float* out = (float*)outp;
                    *(float2*)(out + (size_t)r0 * CC + n)       = make_float2(v00, v01);
                    *(float2*)(out + (size_t)(r0 + 8) * CC + n) = make_float2(v10, v11);
                } else {
                    __half* out = (__half*)outp;
                    int b = r0 >> 11, t = r0 & 2047;
                    int h = n >> 6,  d = n & 63;
                    size_t addr = (((size_t)(b * NH + h) * TT + t) << 6) + d;
                    *(__half2*)(out + addr) = __floats2half2_rn(v00 * scale, v01 * scale);
                    *(__half2*)(out + addr + 8 * 64) = __floats2half2_rn(v10 * scale, v11 * scale);
                }
            }
        }
    }
#undef GEMM_ISSUE
}

// ============================================================================
// Flash attention fp16: Q tile 128 (8 warps x 16 rows), KV tiles 64, cp.async
// double-buffered. S/softmax/O in registers; P repacked in registers (f16
// C-frag == A-frag layout). V pre-transposed (B,H,D,T).
// ============================================================================
#define HLD 72
#define ATT_SMEM ((2 * 64 * HLD + 2 * 64 * HLD + 128 * HLD) * 2)

__global__ __launch_bounds__(256, 1) void attn_kernel(
    const __half* __restrict__ q, const __half* __restrict__ k,
    const __half* __restrict__ v, __half* __restrict__ y)
{
    extern __shared__ __half smh[];
    __half* Ks = smh;                       // 2 x 64 x HLD   [token][d]
    __half* Vs = smh + 2 * 64 * HLD;        // 2 x 64 x HLD   [d][token]
    __half* Qs = smh + 4 * 64 * HLD;        // 128 x HLD      [q][d], reused for out

    const int qt = (gridDim.x - 1) - blockIdx.x;
    const int h  = blockIdx.y;
    const int b  = blockIdx.z;
    const int tid  = threadIdx.x;
    const int w    = tid >> 5;
    const int lane = tid & 31;
    const int grp  = lane >> 2;
    const int tg   = lane & 3;

    const __half* qb  = q + ((size_t)(b * NH + h) * TT + (size_t)qt * 128) * HS;
    const __half* kb0 = k + (size_t)(b * NH + h) * TT * HS;
    const __half* vb0 = v + (size_t)(b * NH + h) * HS * TT;   // [d][t]

    const uint32_t ks_addr = (uint32_t)__cvta_generic_to_shared(Ks);
    const uint32_t vs_addr = (uint32_t)__cvta_generic_to_shared(Vs);
    const uint32_t qs_addr = (uint32_t)__cvta_generic_to_shared(Qs);

#define KV_ISSUE(KT_, BUF_)                                                     \
    do {                                                                        \
        uint32_t kbase = ks_addr + (uint32_t)(BUF_) * 64 * HLD * 2;             \
        uint32_t vbase = vs_addr + (uint32_t)(BUF_) * 64 * HLD * 2;             \
        _Pragma("unroll")                                                       \
        for (int c = 0; c < 2; c++) {                                           \
            int id = c * 256 + tid;                                             \
            int row = id >> 3, kc = id & 7;                                     \
            cp16(kbase + (row * HLD + kc * 8) * 2,                              \
                 kb0 + ((size_t)(KT_) * 64 + row) * HS + kc * 8);               \
            cp16(vbase + (row * HLD + kc * 8) * 2,                              \
                 vb0 + (size_t)row * TT + (KT_) * 64 + kc * 8);                 \
        }                                                                       \
    } while (0)

    const int nk = 2 * qt + 2;

    KV_ISSUE(0, 0);
    CP_COMMIT();
    // stage Q
#pragma unroll
    for (int c = 0; c < 4; c++) {
        int id = c * 256 + tid;
        int row = id >> 3, kc = id & 7;
        cp16(qs_addr + (row * HLD + kc * 8) * 2, qb + (size_t)row * HS + kc * 8);
    }
    CP_COMMIT();
    CP_WAIT(0);
    __syncthreads();

    const __half* Qw = Qs + w * 16 * HLD;
    uint32_t qf[4][4];
#pragma unroll
    for (int ks = 0; ks < 4; ks++) {
        qf[ks][0] = *(const uint32_t*)(Qw + grp       * HLD + ks * 16 + 2 * tg);
        qf[ks][1] = *(const uint32_t*)(Qw + (grp + 8) * HLD + ks * 16 + 2 * tg);
        qf[ks][2] = *(const uint32_t*)(Qw + grp       * HLD + ks * 16 + 2 * tg + 8);
        qf[ks][3] = *(const uint32_t*)(Qw + (grp + 8) * HLD + ks * 16 + 2 * tg + 8);
    }

    float oacc[8][4];
#pragma unroll
    for (int j = 0; j < 8; j++)
#pragma unroll
        for (int c = 0; c < 4; c++) oacc[j][c] = 0.0f;

    float m0r = -1e30f, m1r = -1e30f, l0 = 0.0f, l1 = 0.0f;

    const int wrb  = qt * 128 + w * 16;
    const int row0 = wrb + grp;
    const int row1 = row0 + 8;

#pragma unroll 1
    for (int kt = 0; kt < nk; kt++) {
        const int buf = kt & 1;
        if (kt + 1 < nk) { KV_ISSUE(kt + 1, buf ^ 1); CP_COMMIT(); }

        const __half* Kb = Ks + buf * 64 * HLD;
        const __half* Vb = Vs + buf * 64 * HLD;

        if (kt * 64 <= wrb + 15) {
            // ---- S = Q K^T
            float sacc[8][4];
#pragma unroll
            for (int j = 0; j < 8; j++)
#pragma unroll
                for (int c = 0; c < 4; c++) sacc[j][c] = 0.0f;

#pragma unroll
            for (int j = 0; j < 8; j++) {
#pragma unroll
                for (int ks = 0; ks < 4; ks++) {
                    uint32_t b0 = *(const uint32_t*)(Kb + (j * 8 + grp) * HLD + ks * 16 + 2 * tg);
                    uint32_t b1 = *(const uint32_t*)(Kb + (j * 8 + grp) * HLD + ks * 16 + 2 * tg + 8);
                    mma_f16(sacc[j], qf[ks], b0, b1);
                }
            }

            // ---- causal mask
            if (kt * 64 + 63 > wrb) {
#pragma unroll
                for (int j = 0; j < 8; j++) {
#pragma unroll
                    for (int c = 0; c < 2; c++) {
                        int col = kt * 64 + j * 8 + 2 * tg + c;
                        if (col > row0) sacc[j][c]     = -1e30f;
                        if (col > row1) sacc[j][2 + c] = -1e30f;
                    }
                }
            }

            // ---- online softmax (registers)
            float mx0 = -1e30f, mx1 = -1e30f;
#pragma unroll
            for (int j = 0; j < 8; j++) {
                mx0 = fmaxf(mx0, fmaxf(sacc[j][0], sacc[j][1]));
                mx1 = fmaxf(mx1, fmaxf(sacc[j][2], sacc[j][3]));
            }
            mx0 = fmaxf(mx0, __shfl_xor_sync(0xffffffffu, mx0, 1));
            mx0 = fmaxf(mx0, __shfl_xor_sync(0xffffffffu, mx0, 2));
            mx1 = fmaxf(mx1, __shfl_xor_sync(0xffffffffu, mx1, 1));
            mx1 = fmaxf(mx1, __shfl_xor_sync(0xffffffffu, mx1, 2));

            float mn0 = fmaxf(m0r, mx0), mn1 = fmaxf(m1r, mx1);
            float a0 = __expf(m0r - mn0), a1 = __expf(m1r - mn1);
            m0r = mn0; m1r = mn1;

            float s0 = 0.0f, s1 = 0.0f;
#pragma unroll
            for (int j = 0; j < 8; j++) {
                float p;
                p = __expf(sacc[j][0] - mn0); sacc[j][0] = p; s0 += p;
                p = __expf(sacc[j][1] - mn0); sacc[j][1] = p; s0 += p;
                p = __expf(sacc[j][2] - mn1); sacc[j][2] = p; s1 += p;
                p = __expf(sacc[j][3] - mn1); sacc[j][3] = p; s1 += p;
            }
            s0 += __shfl_xor_sync(0xffffffffu, s0, 1);
            s0 += __shfl_xor_sync(0xffffffffu, s0, 2);
            s1 += __shfl_xor_sync(0xffffffffu, s1, 1);
            s1 += __shfl_xor_sync(0xffffffffu, s1, 2);
            l0 = l0 * a0 + s0;
            l1 = l1 * a1 + s1;

#pragma unroll
            for (int j = 0; j < 8; j++) {
                oacc[j][0] *= a0; oacc[j][1] *= a0;
                oacc[j][2] *= a1; oacc[j][3] *= a1;
            }

            // ---- O += P V : P repacked in registers (C-frag -> A-frag)
#pragma unroll
            for (int ks = 0; ks < 4; ks++) {
                uint32_t pa[4];
                pa[0] = pack_h2(sacc[2 * ks][0],     sacc[2 * ks][1]);
                pa[1] = pack_h2(sacc[2 * ks][2],     sacc[2 * ks][3]);
                pa[2] = pack_h2(sacc[2 * ks + 1][0], sacc[2 * ks + 1][1]);
                pa[3] = pack_h2(sacc[2 * ks + 1][2], sacc[2 * ks + 1][3]);
#pragma unroll
                for (int j = 0; j < 8; j++) {
                    uint32_t b0 = *(const uint32_t*)(Vb + (j * 8 + grp) * HLD + ks * 16 + 2 * tg);
                    uint32_t b1 = *(const uint32_t*)(Vb + (j * 8 + grp) * HLD + ks * 16 + 2 * tg + 8);
                    mma_f16(oacc[j], pa, b0, b1);
                }
            }
        }

        if (kt + 1 < nk) CP_WAIT(0);
        __syncthreads();
    }

    // ---- normalize, write y (B,T,C) fp16 via staging
    float inv0 = 1.0f / l0, inv1 = 1.0f / l1;
    __half* Ow = Qs + w * 16 * HLD;
#pragma unroll
    for (int j = 0; j < 8; j++) {
        *(uint32_t*)(Ow + grp       * HLD + j * 8 + 2 * tg) =
            pack_h2(oacc[j][0] * inv0, oacc[j][1] * inv0);
        *(uint32_t*)(Ow + (grp + 8) * HLD + j * 8 + 2 * tg) =
            pack_h2(oacc[j][2] * inv1, oacc[j][3] * inv1);
    }
    __syncwarp();

    __half* yb = y + ((size_t)b * TT + qt * 128 + w * 16) * CC + h * HS;
#pragma unroll
    for (int idx = lane; idx < 128; idx += 32) {
        int r = idx >> 3, f = idx & 7;
        *(float4*)(yb + (size_t)r * CC + f * 8) = *(const float4*)(Ow + r * HLD + f * 8);
    }
#undef KV_ISSUE
}

// ============================================================================
// launch
// ============================================================================
extern "C" void kernel_launch(void* const* d_in, const int* in_sizes, int n_in,
                              void* d_out, int out_size)
{
    const float* x  = (const float*)d_in[0];
    const float* Wk = (const float*)d_in[1];
    const float* bk = (const float*)d_in[2];
    const float* Wq = (const float*)d_in[3];
    const float* bq = (const float*)d_in[4];
    const float* Wv = (const float*)d_in[5];
    const float* bv = (const float*)d_in[6];
    const float* Wo = (const float*)d_in[7];
    const float* bo = (const float*)d_in[8];
    float* out = (float*)d_out;

    __half *qp, *kp, *vp, *yp, *xc, *wq, *wk, *wv, *wo;
    cudaGetSymbolAddress((void**)&qp, g_q);
    cudaGetSymbolAddress((void**)&kp, g_k);
    cudaGetSymbolAddress((void**)&vp, g_v);
    cudaGetSymbolAddress((void**)&yp, g_y);
    cudaGetSymbolAddress((void**)&xc, g_xc);
    cudaGetSymbolAddress((void**)&wq, g_wq);
    cudaGetSymbolAddress((void**)&wk, g_wk);
    cudaGetSymbolAddress((void**)&wv, g_wv);
    cudaGetSymbolAddress((void**)&wo, g_wo);

    cudaFuncSetAttribute(gemm_f16_kernel,
                         cudaFuncAttributeMaxDynamicSharedMemorySize, GEMM_SMEM);
    cudaFuncSetAttribute(attn_kernel,
                         cudaFuncAttributeMaxDynamicSharedMemorySize, ATT_SMEM);

    // prep
    int nx4 = (BB * TT * CC) / 4;
    round_half_kernel<<<nx4 / 256, 256>>>(x, xc, nx4);
    dim3 tgrid(CC / 32, CC / 32), tblk(32, 8);
    transpose_w_kernel<<<tgrid, tblk>>>(Wq, wq);
    transpose_w_kernel<<<tgrid, tblk>>>(Wk, wk);
    transpose_w_kernel<<<tgrid, tblk>>>(Wv, wv);
    transpose_w_kernel<<<tgrid, tblk>>>(Wo, wo);

    dim3 ggrid(CC / 128, (BB * TT) / 128);
    gemm_f16_kernel<<<ggrid, 128, GEMM_SMEM>>>(xc, wq, bq, qp, 1, 0.125f);
    gemm_f16_kernel<<<ggrid, 128, GEMM_SMEM>>>(xc, wk, bk, kp, 1, 1.0f);
    gemm_f16_kernel<<<ggrid, 128, GEMM_SMEM>>>(xc, wv, bv, vp, 2, 1.0f);

    dim3 agrid(TT / 128, NH, BB);
    attn_kernel<<<agrid, 256, ATT_SMEM>>>(qp, kp, vp, yp);

    gemm_f16_kernel<<<ggrid, 128, GEMM_SMEM>>>(yp, wo, bo, out, 0, 1.0f);
}

// round 13
// speedup vs baseline: 5.3938x; 1.1868x over previous
#include <cuda_runtime.h>
#include <cuda_fp16.h>
#include <cstdint>

#define BB 4
#define TT 2048
#define CC 1024
#define NH 16
#define HS 64

// ---------------- scratch (allocation-free: __device__ globals) -------------
__device__ __half g_q[BB * TT * CC];    // (B,H,T,D) fp16, pre-scaled by 0.125
__device__ __half g_k[BB * TT * CC];    // (B,H,T,D) fp16
__device__ __half g_v[BB * TT * CC];    // (B,H,D,T) fp16  (TRANSPOSED)
__device__ __half g_y[BB * TT * CC];    // (B,T,C)  fp16
__device__ __half g_xc[BB * TT * CC];   // x fp16
__device__ __half g_wq[CC * CC];        // W^T fp16 [n][k]
__device__ __half g_wk[CC * CC];
__device__ __half g_wv[CC * CC];
__device__ __half g_wo[CC * CC];

__device__ __forceinline__ void cp16(uint32_t dst, const void* src) {
    asm volatile("cp.async.cg.shared.global [%0], [%1], 16;\n" :: "r"(dst), "l"(src));
}
#define CP_COMMIT() asm volatile("cp.async.commit_group;\n" ::: "memory")
#define CP_WAIT(N)  asm volatile("cp.async.wait_group %0;\n" :: "n"(N) : "memory")

__device__ __forceinline__ void mma_f16(
    float d[4], const uint32_t a[4], uint32_t b0, uint32_t b1)
{
    asm volatile(
        "mma.sync.aligned.m16n8k16.row.col.f32.f16.f16.f32 "
        "{%0,%1,%2,%3}, {%4,%5,%6,%7}, {%8,%9}, {%0,%1,%2,%3};\n"
        : "+f"(d[0]), "+f"(d[1]), "+f"(d[2]), "+f"(d[3])
        : "r"(a[0]), "r"(a[1]), "r"(a[2]), "r"(a[3]), "r"(b0), "r"(b1));
}

__device__ __forceinline__ void ldsm_x4(
    uint32_t& r0, uint32_t& r1, uint32_t& r2, uint32_t& r3, uint32_t addr)
{
    asm volatile("ldmatrix.sync.aligned.m8n8.x4.shared.b16 {%0,%1,%2,%3}, [%4];"
                 : "=r"(r0), "=r"(r1), "=r"(r2), "=r"(r3) : "r"(addr));
}

__device__ __forceinline__ uint32_t pack_h2(float lo, float hi) {
    __half2 h = __floats2half2_rn(lo, hi);
    return *(uint32_t*)&h;
}

__device__ __forceinline__ uint32_t smem_u32(const void* p) {
    uint32_t a;
    asm("{ .reg .u64 t; cvta.to.shared.u64 t, %1; cvt.u32.u64 %0, t; }" : "=r"(a) : "l"(p));
    return a;
}

// ============================================================================
// prep: fp32 -> fp16
// ============================================================================
__global__ void round_half_kernel(const float* __restrict__ in,
                                  __half* __restrict__ out, int n4)
{
    int i = blockIdx.x * blockDim.x + threadIdx.x;
    if (i < n4) {
        float4 v = ((const float4*)in)[i];
        __half2* o = (__half2*)(out + (size_t)i * 4);
        o[0] = __floats2half2_rn(v.x, v.y);
        o[1] = __floats2half2_rn(v.z, v.w);
    }
}

// prep: W [k][n] fp32 -> W^T [n][k] fp16 (tiled transpose)
__global__ void transpose_w_kernel(const float* __restrict__ in,
                                   __half* __restrict__ out)
{
    __shared__ float t[32][33];
    int bx = blockIdx.x * 32, by = blockIdx.y * 32;
#pragma unroll
    for (int i = 0; i < 32; i += 8)
        t[threadIdx.y + i][threadIdx.x] = in[(size_t)(by + threadIdx.y + i) * CC + bx + threadIdx.x];
    __syncthreads();
#pragma unroll
    for (int i = 0; i < 32; i += 8)
        out[(size_t)(bx + threadIdx.y + i) * CC + by + threadIdx.x] =
            __float2half_rn(t[threadIdx.x][threadIdx.y + i]);
}

// ============================================================================
// GEMM: [8192,1024] = A(half) @ W^T(half,[n][k]) + bias, fp32 accum.
// CTA 128x128, 4 warps (warp 64x64), BK=32, 3-stage cp.async, ldmatrix frags.
// mode 0: fp32 row-major out. mode 1: half (B,H,T,D), *scale. mode 2: half
// (B,H,D,T) transposed via smem-staged warp transpose.
// ============================================================================
#define G_LD 40
#define G_NST 3
#define G_STAGE (128 * G_LD)
#define GEMM_SMEM (G_NST * 2 * G_STAGE * 2)

__global__ __launch_bounds__(128, 2) void gemm_f16_kernel(
    const __half* __restrict__ A, const __half* __restrict__ Wt,
    const float* __restrict__ bias, void* __restrict__ outp,
    int mode, float scale)
{
    extern __shared__ __half smh[];
    __half* As = smh;
    __half* Bs = smh + G_NST * G_STAGE;

    const int tid  = threadIdx.x;
    const int wid  = tid >> 5;
    const int lane = tid & 31;
    const int grp  = lane >> 2;
    const int tg   = lane & 3;

    const int m0 = blockIdx.y * 128;
    const int n0 = blockIdx.x * 128;
    const int warp_m = wid >> 1;
    const int warp_n = wid & 1;

    const uint32_t as_addr = smem_u32(As);
    const uint32_t bs_addr = smem_u32(Bs);

    // ldmatrix per-lane row/k offsets (verified vs PTX fragment tables)
    const int a_lrow = (lane & 7) + ((lane >> 3) & 1) * 8;   // A-frag pattern
    const int a_lkof = (lane >> 4) * 8;
    const int b_lrow = (lane & 7) + ((lane >> 4) & 1) * 8;   // B-frag pair pattern
    const int b_lkof = ((lane >> 3) & 1) * 8;

#define GEMM_ISSUE(BUF, K0)                                                     \
    do {                                                                        \
        uint32_t sa = as_addr + (uint32_t)(BUF) * G_STAGE * 2;                  \
        uint32_t sb = bs_addr + (uint32_t)(BUF) * G_STAGE * 2;                  \
        _Pragma("unroll")                                                       \
        for (int c = 0; c < 4; c++) {                                           \
            int id = c * 128 + tid;                                             \
            int row = id >> 2, kc = id & 3;                                     \
            cp16(sa + (row * G_LD + kc * 8) * 2,                                \
                 A  + (size_t)(m0 + row) * CC + (K0) + kc * 8);                 \
            cp16(sb + (row * G_LD + kc * 8) * 2,                                \
                 Wt + (size_t)(n0 + row) * CC + (K0) + kc * 8);                 \
        }                                                                       \
    } while (0)

    float acc[4][8][4];
#pragma unroll
    for (int i = 0; i < 4; i++)
#pragma unroll
        for (int j = 0; j < 8; j++)
#pragma unroll
            for (int c = 0; c < 4; c++) acc[i][j][c] = 0.0f;

    GEMM_ISSUE(0, 0);  CP_COMMIT();
    GEMM_ISSUE(1, 32); CP_COMMIT();
    CP_WAIT(1);
    __syncthreads();

    int buf = 0;
#pragma unroll 1
    for (int s = 0; s < 32; s++) {
        if (s + 2 < 32) { GEMM_ISSUE((s + 2) % G_NST, (s + 2) * 32); }
        CP_COMMIT();

        const uint32_t ab = as_addr + (uint32_t)buf * G_STAGE * 2;
        const uint32_t bb = bs_addr + (uint32_t)buf * G_STAGE * 2;

#pragma unroll
        for (int kk = 0; kk < 2; kk++) {
            uint32_t af[4][4];
            uint32_t bf[8][2];
#pragma unroll
            for (int i = 0; i < 4; i++) {
                int row = warp_m * 64 + i * 16 + a_lrow;
                ldsm_x4(af[i][0], af[i][1], af[i][2], af[i][3],
                        ab + (row * G_LD + kk * 16 + a_lkof) * 2);
            }
#pragma unroll
            for (int j2 = 0; j2 < 4; j2++) {
                int row = warp_n * 64 + j2 * 16 + b_lrow;
                ldsm_x4(bf[2 * j2][0], bf[2 * j2][1], bf[2 * j2 + 1][0], bf[2 * j2 + 1][1],
                        bb + (row * G_LD + kk * 16 + b_lkof) * 2);
            }
#pragma unroll
            for (int i = 0; i < 4; i++)
#pragma unroll
                for (int j = 0; j < 8; j++)
                    mma_f16(acc[i][j], af[i], bf[j][0], bf[j][1]);
        }

        CP_WAIT(1);
        __syncthreads();
        buf++; if (buf == G_NST) buf = 0;
    }

    // ---- epilogue
    float2 bj[8];
#pragma unroll
    for (int j = 0; j < 8; j++)
        bj[j] = *(const float2*)(bias + n0 + warp_n * 64 + j * 8 + tg * 2);

    if (mode == 2) {
        // V: warp transpose 64x64 through smem, write (B,H,D,T)
        __half* Ts = smh + wid * (64 * 72);
#pragma unroll
        for (int i = 0; i < 4; i++) {
            int r = i * 16 + grp;
#pragma unroll
            for (int j = 0; j < 8; j++) {
                int c = j * 8 + 2 * tg;
                Ts[c * 72 + r]           = __float2half_rn(acc[i][j][0] + bj[j].x);
                Ts[(c + 1) * 72 + r]     = __float2half_rn(acc[i][j][1] + bj[j].y);
                Ts[c * 72 + r + 8]       = __float2half_rn(acc[i][j][2] + bj[j].x);
                Ts[(c + 1) * 72 + r + 8] = __float2half_rn(acc[i][j][3] + bj[j].y);
            }
        }
        __syncwarp();
        __half* vout = (__half*)outp;
        const int b = m0 >> 11;
        const int h = (n0 + warp_n * 64) >> 6;
        const int t0 = (m0 & 2047) + warp_m * 64;   // batch-local token
#pragma unroll
        for (int idx = lane; idx < 512; idx += 32) {
            int c = idx >> 3, f = idx & 7;
            float4 val = *(const float4*)(Ts + c * 72 + f * 8);
            *(float4*)(vout + ((size_t)(b * NH + h) * HS + c) * TT + t0 + f * 8) = val;
        }
    } else {
#pragma unroll
        for (int i = 0; i < 4; i++) {
            int r0 = m0 + warp_m * 64 + i * 16 + grp;
#pragma unroll
            for (int j = 0; j < 8; j++) {
                int n = n0 + warp_n * 64 + j * 8 + tg * 2;
                float v00 = acc[i][j][0] + bj[j].x;
                float v01 = acc[i][j][1] + bj[j].y;
                float v10 = acc[i][j][2] + bj[j].x;
                float v11 = acc[i][j][3] + bj[j].y;
                if (mode == 0) {
                    float* out = (float*)outp;
                    *(float2*)(out + (size_t)r0 * CC + n)       = make_float2(v00, v01);
                    *(float2*)(out + (size_t)(r0 + 8) * CC + n) = make_float2(v10, v11);
                } else {
                    __half* out = (__half*)outp;
                    int b = r0 >> 11, t = r0 & 2047;
                    int h = n >> 6,  d = n & 63;
                    size_t addr = (((size_t)(b * NH + h) * TT + t) << 6) + d;
                    *(__half2*)(out + addr) = __floats2half2_rn(v00 * scale, v01 * scale);
                    *(__half2*)(out + addr + 8 * 64) = __floats2half2_rn(v10 * scale, v11 * scale);
                }
            }
        }
    }
#undef GEMM_ISSUE
}

// ============================================================================
// Flash attention fp16: Q tile 128 (8 warps x 16 rows), KV tiles 64, cp.async
// double-buffered, register-resident S/softmax/O, P register-repacked,
// V pre-transposed (B,H,D,T). Fragment loads via ldmatrix.
// ============================================================================
#define HLD 72
#define ATT_SMEM ((2 * 64 * HLD + 2 * 64 * HLD + 128 * HLD) * 2)

__global__ __launch_bounds__(256, 1) void attn_kernel(
    const __half* __restrict__ q, const __half* __restrict__ k,
    const __half* __restrict__ v, __half* __restrict__ y)
{
    extern __shared__ __half smh[];
    __half* Ks = smh;                       // 2 x 64 x HLD   [token][d]
    __half* Vs = smh + 2 * 64 * HLD;        // 2 x 64 x HLD   [d][token]
    __half* Qs = smh + 4 * 64 * HLD;        // 128 x HLD      [q][d], reused for out

    const int qt = (gridDim.x - 1) - blockIdx.x;
    const int h  = blockIdx.y;
    const int b  = blockIdx.z;
    const int tid  = threadIdx.x;
    const int w    = tid >> 5;
    const int lane = tid & 31;
    const int grp  = lane >> 2;
    const int tg   = lane & 3;

    const __half* qb  = q + ((size_t)(b * NH + h) * TT + (size_t)qt * 128) * HS;
    const __half* kb0 = k + (size_t)(b * NH + h) * TT * HS;
    const __half* vb0 = v + (size_t)(b * NH + h) * HS * TT;

    const uint32_t ks_addr = smem_u32(Ks);
    const uint32_t vs_addr = smem_u32(Vs);
    const uint32_t qs_addr = smem_u32(Qs);

    const int a_lrow = (lane & 7) + ((lane >> 3) & 1) * 8;   // A-frag ldmatrix
    const int a_lkof = (lane >> 4) * 8;
    const int b_lrow = (lane & 7) + ((lane >> 4) & 1) * 8;   // B-frag pair ldmatrix
    const int b_lkof = ((lane >> 3) & 1) * 8;

#define KV_ISSUE(KT_, BUF_)                                                     \
    do {                                                                        \
        uint32_t kbase = ks_addr + (uint32_t)(BUF_) * 64 * HLD * 2;             \
        uint32_t vbase = vs_addr + (uint32_t)(BUF_) * 64 * HLD * 2;             \
        _Pragma("unroll")                                                       \
        for (int c = 0; c < 2; c++) {                                           \
            int id = c * 256 + tid;                                             \
            int row = id >> 3, kc = id & 7;                                     \
            cp16(kbase + (row * HLD + kc * 8) * 2,                              \
                 kb0 + ((size_t)(KT_) * 64 + row) * HS + kc * 8);               \
            cp16(vbase + (row * HLD + kc * 8) * 2,                              \
                 vb0 + (size_t)row * TT + (KT_) * 64 + kc * 8);                 \
        }                                                                       \
    } while (0)

    const int nk = 2 * qt + 2;

    KV_ISSUE(0, 0);
    CP_COMMIT();
    // stage Q
#pragma unroll
    for (int c = 0; c < 4; c++) {
        int id = c * 256 + tid;
        int row = id >> 3, kc = id & 7;
        cp16(qs_addr + (row * HLD + kc * 8) * 2, qb + (size_t)row * HS + kc * 8);
    }
    CP_COMMIT();
    CP_WAIT(0);
    __syncthreads();

    const uint32_t qw_addr = qs_addr + (uint32_t)w * 16 * HLD * 2;
    uint32_t qf[4][4];
#pragma unroll
    for (int ks = 0; ks < 4; ks++)
        ldsm_x4(qf[ks][0], qf[ks][1], qf[ks][2], qf[ks][3],
                qw_addr + (a_lrow * HLD + ks * 16 + a_lkof) * 2);

    float oacc[8][4];
#pragma unroll
    for (int j = 0; j < 8; j++)
#pragma unroll
        for (int c = 0; c < 4; c++) oacc[j][c] = 0.0f;

    float m0r = -1e30f, m1r = -1e30f, l0 = 0.0f, l1 = 0.0f;

    const int wrb  = qt * 128 + w * 16;
    const int row0 = wrb + grp;
    const int row1 = row0 + 8;

#pragma unroll 1
    for (int kt = 0; kt < nk; kt++) {
        const int buf = kt & 1;
        if (kt + 1 < nk) { KV_ISSUE(kt + 1, buf ^ 1); CP_COMMIT(); }

        const uint32_t kb = ks_addr + (uint32_t)buf * 64 * HLD * 2;
        const uint32_t vb = vs_addr + (uint32_t)buf * 64 * HLD * 2;

        if (kt * 64 <= wrb + 15) {
            // ---- S = Q K^T
            float sacc[8][4];
#pragma unroll
            for (int j = 0; j < 8; j++)
#pragma unroll
                for (int c = 0; c < 4; c++) sacc[j][c] = 0.0f;

#pragma unroll
            for (int ks = 0; ks < 4; ks++) {
                uint32_t kf[8][2];
#pragma unroll
                for (int j2 = 0; j2 < 4; j2++) {
                    int row = j2 * 16 + b_lrow;
                    ldsm_x4(kf[2 * j2][0], kf[2 * j2][1], kf[2 * j2 + 1][0], kf[2 * j2 + 1][1],
                            kb + (row * HLD + ks * 16 + b_lkof) * 2);
                }
#pragma unroll
                for (int j = 0; j < 8; j++)
                    mma_f16(sacc[j], qf[ks], kf[j][0], kf[j][1]);
            }

            // ---- causal mask
            if (kt * 64 + 63 > wrb) {
#pragma unroll
                for (int j = 0; j < 8; j++) {
#pragma unroll
                    for (int c = 0; c < 2; c++) {
                        int col = kt * 64 + j * 8 + 2 * tg + c;
                        if (col > row0) sacc[j][c]     = -1e30f;
                        if (col > row1) sacc[j][2 + c] = -1e30f;
                    }
                }
            }

            // ---- online softmax (registers)
            float mx0 = -1e30f, mx1 = -1e30f;
#pragma unroll
            for (int j = 0; j < 8; j++) {
                mx0 = fmaxf(mx0, fmaxf(sacc[j][0], sacc[j][1]));
                mx1 = fmaxf(mx1, fmaxf(sacc[j][2], sacc[j][3]));
            }
            mx0 = fmaxf(mx0, __shfl_xor_sync(0xffffffffu, mx0, 1));
            mx0 = fmaxf(mx0, __shfl_xor_sync(0xffffffffu, mx0, 2));
            mx1 = fmaxf(mx1, __shfl_xor_sync(0xffffffffu, mx1, 1));
            mx1 = fmaxf(mx1, __shfl_xor_sync(0xffffffffu, mx1, 2));

            float mn0 = fmaxf(m0r, mx0), mn1 = fmaxf(m1r, mx1);
            float a0 = __expf(m0r - mn0), a1 = __expf(m1r - mn1);
            m0r = mn0; m1r = mn1;

            float s0 = 0.0f, s1 = 0.0f;
#pragma unroll
            for (int j = 0; j < 8; j++) {
                float p;
                p = __expf(sacc[j][0] - mn0); sacc[j][0] = p; s0 += p;
                p = __expf(sacc[j][1] - mn0); sacc[j][1] = p; s0 += p;
                p = __expf(sacc[j][2] - mn1); sacc[j][2] = p; s1 += p;
                p = __expf(sacc[j][3] - mn1); sacc[j][3] = p; s1 += p;
            }
            s0 += __shfl_xor_sync(0xffffffffu, s0, 1);
            s0 += __shfl_xor_sync(0xffffffffu, s0, 2);
            s1 += __shfl_xor_sync(0xffffffffu, s1, 1);
            s1 += __shfl_xor_sync(0xffffffffu, s1, 2);
            l0 = l0 * a0 + s0;
            l1 = l1 * a1 + s1;

#pragma unroll
            for (int j = 0; j < 8; j++) {
                oacc[j][0] *= a0; oacc[j][1] *= a0;
                oacc[j][2] *= a1; oacc[j][3] *= a1;
            }

            // ---- O += P V : P repacked in registers (C-frag -> A-frag)
#pragma unroll
            for (int ks = 0; ks < 4; ks++) {
                uint32_t pa[4];
                pa[0] = pack_h2(sacc[2 * ks][0],     sacc[2 * ks][1]);
                pa[1] = pack_h2(sacc[2 * ks][2],     sacc[2 * ks][3]);
                pa[2] = pack_h2(sacc[2 * ks + 1][0], sacc[2 * ks + 1][1]);
                pa[3] = pack_h2(sacc[2 * ks + 1][2], sacc[2 * ks + 1][3]);
                uint32_t vf[8][2];
#pragma unroll
                for (int j2 = 0; j2 < 4; j2++) {
                    int row = j2 * 16 + b_lrow;
                    ldsm_x4(vf[2 * j2][0], vf[2 * j2][1], vf[2 * j2 + 1][0], vf[2 * j2 + 1][1],
                            vb + (row * HLD + ks * 16 + b_lkof) * 2);
                }
#pragma unroll
                for (int j = 0; j < 8; j++)
                    mma_f16(oacc[j], pa, vf[j][0], vf[j][1]);
            }
        }

        if (kt + 1 < nk) CP_WAIT(0);
        __syncthreads();
    }

    // ---- normalize, write y (B,T,C) fp16 via staging
    float inv0 = 1.0f / l0, inv1 = 1.0f / l1;
    __half* Ow = Qs + w * 16 * HLD;
#pragma unroll
    for (int j = 0; j < 8; j++) {
        *(uint32_t*)(Ow + grp       * HLD + j * 8 + 2 * tg) =
            pack_h2(oacc[j][0] * inv0, oacc[j][1] * inv0);
        *(uint32_t*)(Ow + (grp + 8) * HLD + j * 8 + 2 * tg) =
            pack_h2(oacc[j][2] * inv1, oacc[j][3] * inv1);
    }
    __syncwarp();

    __half* yb = y + ((size_t)b * TT + qt * 128 + w * 16) * CC + h * HS;
#pragma unroll
    for (int idx = lane; idx < 128; idx += 32) {
        int r = idx >> 3, f = idx & 7;
        *(float4*)(yb + (size_t)r * CC + f * 8) = *(const float4*)(Ow + r * HLD + f * 8);
    }
#undef KV_ISSUE
}

// ============================================================================
// launch
// ============================================================================
extern "C" void kernel_launch(void* const* d_in, const int* in_sizes, int n_in,
                              void* d_out, int out_size)
{
    const float* x  = (const float*)d_in[0];
    const float* Wk = (const float*)d_in[1];
    const float* bk = (const float*)d_in[2];
    const float* Wq = (const float*)d_in[3];
    const float* bq = (const float*)d_in[4];
    const float* Wv = (const float*)d_in[5];
    const float* bv = (const float*)d_in[6];
    const float* Wo = (const float*)d_in[7];
    const float* bo = (const float*)d_in[8];
    float* out = (float*)d_out;

    __half *qp, *kp, *vp, *yp, *xc, *wq, *wk, *wv, *wo;
    cudaGetSymbolAddress((void**)&qp, g_q);
    cudaGetSymbolAddress((void**)&kp, g_k);
    cudaGetSymbolAddress((void**)&vp, g_v);
    cudaGetSymbolAddress((void**)&yp, g_y);
    cudaGetSymbolAddress((void**)&xc, g_xc);
    cudaGetSymbolAddress((void**)&wq, g_wq);
    cudaGetSymbolAddress((void**)&wk, g_wk);
    cudaGetSymbolAddress((void**)&wv, g_wv);
    cudaGetSymbolAddress((void**)&wo, g_wo);

    cudaFuncSetAttribute(gemm_f16_kernel,
                         cudaFuncAttributeMaxDynamicSharedMemorySize, GEMM_SMEM);
    cudaFuncSetAttribute(attn_kernel,
                         cudaFuncAttributeMaxDynamicSharedMemorySize, ATT_SMEM);

    // prep
    int nx4 = (BB * TT * CC) / 4;
    round_half_kernel<<<nx4 / 256, 256>>>(x, xc, nx4);
    dim3 tgrid(CC / 32, CC / 32), tblk(32, 8);
    transpose_w_kernel<<<tgrid, tblk>>>(Wq, wq);
    transpose_w_kernel<<<tgrid, tblk>>>(Wk, wk);
    transpose_w_kernel<<<tgrid, tblk>>>(Wv, wv);
    transpose_w_kernel<<<tgrid, tblk>>>(Wo, wo);

    dim3 ggrid(CC / 128, (BB * TT) / 128);
    gemm_f16_kernel<<<ggrid, 128, GEMM_SMEM>>>(xc, wq, bq, qp, 1, 0.125f);
    gemm_f16_kernel<<<ggrid, 128, GEMM_SMEM>>>(xc, wk, bk, kp, 1, 1.0f);
    gemm_f16_kernel<<<ggrid, 128, GEMM_SMEM>>>(xc, wv, bv, vp, 2, 1.0f);

    dim3 agrid(TT / 128, NH, BB);
    attn_kernel<<<agrid, 256, ATT_SMEM>>>(qp, kp, vp, yp);

    gemm_f16_kernel<<<ggrid, 128, GEMM_SMEM>>>(yp, wo, bo, out, 0, 1.0f);
}

// round 14
// speedup vs baseline: 5.9496x; 1.1030x over previous
#include <cuda_runtime.h>
#include <cuda_fp16.h>
#include <cstdint>

#define BB 4
#define TT 2048
#define CC 1024
#define NH 16
#define HS 64

// ---------------- scratch (allocation-free: __device__ globals) -------------
__device__ __half g_q[BB * TT * CC];    // (B,H,T,D) fp16, pre-scaled by 0.125
__device__ __half g_k[BB * TT * CC];    // (B,H,T,D) fp16
__device__ __half g_v[BB * TT * CC];    // (B,H,D,T) fp16  (TRANSPOSED)
__device__ __half g_y[BB * TT * CC];    // (B,T,C)  fp16
__device__ __half g_xc[BB * TT * CC];   // x fp16
__device__ __half g_wq[CC * CC];        // W^T fp16 [n][k]
__device__ __half g_wk[CC * CC];
__device__ __half g_wv[CC * CC];
__device__ __half g_wo[CC * CC];

__device__ __forceinline__ void cp16(uint32_t dst, const void* src) {
    asm volatile("cp.async.cg.shared.global [%0], [%1], 16;\n" :: "r"(dst), "l"(src));
}
#define CP_COMMIT() asm volatile("cp.async.commit_group;\n" ::: "memory")
#define CP_WAIT(N)  asm volatile("cp.async.wait_group %0;\n" :: "n"(N) : "memory")

__device__ __forceinline__ void mma_f16(
    float d[4], const uint32_t a[4], uint32_t b0, uint32_t b1)
{
    asm volatile(
        "mma.sync.aligned.m16n8k16.row.col.f32.f16.f16.f32 "
        "{%0,%1,%2,%3}, {%4,%5,%6,%7}, {%8,%9}, {%0,%1,%2,%3};\n"
        : "+f"(d[0]), "+f"(d[1]), "+f"(d[2]), "+f"(d[3])
        : "r"(a[0]), "r"(a[1]), "r"(a[2]), "r"(a[3]), "r"(b0), "r"(b1));
}

__device__ __forceinline__ void ldsm_x4(
    uint32_t& r0, uint32_t& r1, uint32_t& r2, uint32_t& r3, uint32_t addr)
{
    asm volatile("ldmatrix.sync.aligned.m8n8.x4.shared.b16 {%0,%1,%2,%3}, [%4];"
                 : "=r"(r0), "=r"(r1), "=r"(r2), "=r"(r3) : "r"(addr));
}

__device__ __forceinline__ uint32_t pack_h2(float lo, float hi) {
    __half2 h = __floats2half2_rn(lo, hi);
    return *(uint32_t*)&h;
}

__device__ __forceinline__ uint32_t smem_u32(const void* p) {
    uint32_t a;
    asm("{ .reg .u64 t; cvta.to.shared.u64 t, %1; cvt.u32.u64 %0, t; }" : "=r"(a) : "l"(p));
    return a;
}

// ============================================================================
// prep: fp32 -> fp16
// ============================================================================
__global__ void round_half_kernel(const float* __restrict__ in,
                                  __half* __restrict__ out, int n4)
{
    int i = blockIdx.x * blockDim.x + threadIdx.x;
    if (i < n4) {
        float4 v = ((const float4*)in)[i];
        __half2* o = (__half2*)(out + (size_t)i * 4);
        o[0] = __floats2half2_rn(v.x, v.y);
        o[1] = __floats2half2_rn(v.z, v.w);
    }
}

// prep: W [k][n] fp32 -> W^T [n][k] fp16 (tiled transpose)
__global__ void transpose_w_kernel(const float* __restrict__ in,
                                   __half* __restrict__ out)
{
    __shared__ float t[32][33];
    int bx = blockIdx.x * 32, by = blockIdx.y * 32;
#pragma unroll
    for (int i = 0; i < 32; i += 8)
        t[threadIdx.y + i][threadIdx.x] = in[(size_t)(by + threadIdx.y + i) * CC + bx + threadIdx.x];
    __syncthreads();
#pragma unroll
    for (int i = 0; i < 32; i += 8)
        out[(size_t)(bx + threadIdx.y + i) * CC + by + threadIdx.x] =
            __float2half_rn(t[threadIdx.x][threadIdx.y + i]);
}

// ============================================================================
// Shared GEMM mainloop: acc[4][8][4] += A[m0:m0+128, :] @ Wt[n0:n0+128, :]^T
// CTA 128x128, 4 warps (warp 64x64), BK=32, 3-stage cp.async, ldmatrix frags.
// ============================================================================
#define G_LD 40
#define G_NST 3
#define G_STAGE (128 * G_LD)
#define GEMM_SMEM (G_NST * 2 * G_STAGE * 2)

__device__ __forceinline__ void gemm_mainloop(
    const __half* __restrict__ A, const __half* __restrict__ Wt,
    int m0, int n0, uint32_t as_addr, uint32_t bs_addr,
    int tid, int warp_m, int warp_n,
    int a_lrow, int a_lkof, int b_lrow, int b_lkof,
    float acc[4][8][4])
{
#define GEMM_ISSUE(BUF, K0)                                                     \
    do {                                                                        \
        uint32_t sa = as_addr + (uint32_t)(BUF) * G_STAGE * 2;                  \
        uint32_t sb = bs_addr + (uint32_t)(BUF) * G_STAGE * 2;                  \
        _Pragma("unroll")                                                       \
        for (int c = 0; c < 4; c++) {                                           \
            int id = c * 128 + tid;                                             \
            int row = id >> 2, kc = id & 3;                                     \
            cp16(sa + (row * G_LD + kc * 8) * 2,                                \
                 A  + (size_t)(m0 + row) * CC + (K0) + kc * 8);                 \
            cp16(sb + (row * G_LD + kc * 8) * 2,                                \
                 Wt + (size_t)(n0 + row) * CC + (K0) + kc * 8);                 \
        }                                                                       \
    } while (0)

    GEMM_ISSUE(0, 0);  CP_COMMIT();
    GEMM_ISSUE(1, 32); CP_COMMIT();
    CP_WAIT(1);
    __syncthreads();

    int buf = 0;
#pragma unroll 1
    for (int s = 0; s < 32; s++) {
        if (s + 2 < 32) { GEMM_ISSUE((s + 2) % G_NST, (s + 2) * 32); }
        CP_COMMIT();

        const uint32_t ab = as_addr + (uint32_t)buf * G_STAGE * 2;
        const uint32_t bb = bs_addr + (uint32_t)buf * G_STAGE * 2;

#pragma unroll
        for (int kk = 0; kk < 2; kk++) {
            uint32_t af[4][4];
            uint32_t bf[8][2];
#pragma unroll
            for (int i = 0; i < 4; i++) {
                int row = warp_m * 64 + i * 16 + a_lrow;
                ldsm_x4(af[i][0], af[i][1], af[i][2], af[i][3],
                        ab + (row * G_LD + kk * 16 + a_lkof) * 2);
            }
#pragma unroll
            for (int j2 = 0; j2 < 4; j2++) {
                int row = warp_n * 64 + j2 * 16 + b_lrow;
                ldsm_x4(bf[2 * j2][0], bf[2 * j2][1], bf[2 * j2 + 1][0], bf[2 * j2 + 1][1],
                        bb + (row * G_LD + kk * 16 + b_lkof) * 2);
            }
#pragma unroll
            for (int i = 0; i < 4; i++)
#pragma unroll
                for (int j = 0; j < 8; j++)
                    mma_f16(acc[i][j], af[i], bf[j][0], bf[j][1]);
        }

        CP_WAIT(1);
        __syncthreads();
        buf++; if (buf == G_NST) buf = 0;
    }
#undef GEMM_ISSUE
}

// ============================================================================
// Fused QKV GEMM: one launch, grid.z selects {Q,K,V}. Tail waves amortized,
// xc L2-resident across z. z=0: Q (scaled 0.125, (B,H,T,D)); z=1: K ((B,H,T,D));
// z=2: V (transposed (B,H,D,T)).
// ============================================================================
__global__ __launch_bounds__(128, 2) void qkv_gemm_kernel(
    const __half* __restrict__ xc,
    const __half* __restrict__ wq, const __half* __restrict__ wk,
    const __half* __restrict__ wv,
    const float* __restrict__ bq, const float* __restrict__ bk,
    const float* __restrict__ bv,
    __half* __restrict__ qp, __half* __restrict__ kp, __half* __restrict__ vp)
{
    extern __shared__ __half smh[];
    const int tid  = threadIdx.x;
    const int wid  = tid >> 5;
    const int lane = tid & 31;
    const int grp  = lane >> 2;
    const int tg   = lane & 3;

    const int z  = blockIdx.z;
    const int m0 = blockIdx.y * 128;
    const int n0 = blockIdx.x * 128;
    const int warp_m = wid >> 1;
    const int warp_n = wid & 1;

    const __half* Wt  = (z == 0) ? wq : (z == 1) ? wk : wv;
    const float* bias = (z == 0) ? bq : (z == 1) ? bk : bv;

    const uint32_t as_addr = smem_u32(smh);
    const uint32_t bs_addr = smem_u32(smh + G_NST * G_STAGE);

    const int a_lrow = (lane & 7) + ((lane >> 3) & 1) * 8;
    const int a_lkof = (lane >> 4) * 8;
    const int b_lrow = (lane & 7) + ((lane >> 4) & 1) * 8;
    const int b_lkof = ((lane >> 3) & 1) * 8;

    float acc[4][8][4];
#pragma unroll
    for (int i = 0; i < 4; i++)
#pragma unroll
        for (int j = 0; j < 8; j++)
#pragma unroll
            for (int c = 0; c < 4; c++) acc[i][j][c] = 0.0f;

    gemm_mainloop(xc, Wt, m0, n0, as_addr, bs_addr, tid, warp_m, warp_n,
                  a_lrow, a_lkof, b_lrow, b_lkof, acc);

    float2 bj[8];
#pragma unroll
    for (int j = 0; j < 8; j++)
        bj[j] = *(const float2*)(bias + n0 + warp_n * 64 + j * 8 + tg * 2);

    if (z == 2) {
        // V: warp transpose 64x64 through smem, write (B,H,D,T)
        __half* Ts = smh + wid * (64 * 72);
#pragma unroll
        for (int i = 0; i < 4; i++) {
            int r = i * 16 + grp;
#pragma unroll
            for (int j = 0; j < 8; j++) {
                int c = j * 8 + 2 * tg;
                Ts[c * 72 + r]           = __float2half_rn(acc[i][j][0] + bj[j].x);
                Ts[(c + 1) * 72 + r]     = __float2half_rn(acc[i][j][1] + bj[j].y);
                Ts[c * 72 + r + 8]       = __float2half_rn(acc[i][j][2] + bj[j].x);
                Ts[(c + 1) * 72 + r + 8] = __float2half_rn(acc[i][j][3] + bj[j].y);
            }
        }
        __syncwarp();
        const int b = m0 >> 11;
        const int h = (n0 + warp_n * 64) >> 6;
        const int t0 = (m0 & 2047) + warp_m * 64;   // batch-local token
#pragma unroll
        for (int idx = lane; idx < 512; idx += 32) {
            int c = idx >> 3, f = idx & 7;
            float4 val = *(const float4*)(Ts + c * 72 + f * 8);
            *(float4*)(vp + ((size_t)(b * NH + h) * HS + c) * TT + t0 + f * 8) = val;
        }
    } else {
        __half* out = (z == 0) ? qp : kp;
        const float scale = (z == 0) ? 0.125f : 1.0f;
#pragma unroll
        for (int i = 0; i < 4; i++) {
            int r0 = m0 + warp_m * 64 + i * 16 + grp;
#pragma unroll
            for (int j = 0; j < 8; j++) {
                int n = n0 + warp_n * 64 + j * 8 + tg * 2;
                int b = r0 >> 11, t = r0 & 2047;
                int h = n >> 6,  d = n & 63;
                size_t addr = (((size_t)(b * NH + h) * TT + t) << 6) + d;
                *(__half2*)(out + addr) =
                    __floats2half2_rn((acc[i][j][0] + bj[j].x) * scale,
                                      (acc[i][j][1] + bj[j].y) * scale);
                *(__half2*)(out + addr + 8 * 64) =
                    __floats2half2_rn((acc[i][j][2] + bj[j].x) * scale,
                                      (acc[i][j][3] + bj[j].y) * scale);
            }
        }
    }
}

// ============================================================================
// Output projection GEMM: y(half) @ Wo^T + bo -> fp32 (B,T,C)
// ============================================================================
__global__ __launch_bounds__(128, 2) void out_gemm_kernel(
    const __half* __restrict__ yh, const __half* __restrict__ wo,
    const float* __restrict__ bo, float* __restrict__ out)
{
    extern __shared__ __half smh[];
    const int tid  = threadIdx.x;
    const int wid  = tid >> 5;
    const int lane = tid & 31;
    const int grp  = lane >> 2;
    const int tg   = lane & 3;

    const int m0 = blockIdx.y * 128;
    const int n0 = blockIdx.x * 128;
    const int warp_m = wid >> 1;
    const int warp_n = wid & 1;

    const uint32_t as_addr = smem_u32(smh);
    const uint32_t bs_addr = smem_u32(smh + G_NST * G_STAGE);

    const int a_lrow = (lane & 7) + ((lane >> 3) & 1) * 8;
    const int a_lkof = (lane >> 4) * 8;
    const int b_lrow = (lane & 7) + ((lane >> 4) & 1) * 8;
    const int b_lkof = ((lane >> 3) & 1) * 8;

    float acc[4][8][4];
#pragma unroll
    for (int i = 0; i < 4; i++)
#pragma unroll
        for (int j = 0; j < 8; j++)
#pragma unroll
            for (int c = 0; c < 4; c++) acc[i][j][c] = 0.0f;

    gemm_mainloop(yh, wo, m0, n0, as_addr, bs_addr, tid, warp_m, warp_n,
                  a_lrow, a_lkof, b_lrow, b_lkof, acc);

    float2 bj[8];
#pragma unroll
    for (int j = 0; j < 8; j++)
        bj[j] = *(const float2*)(bo + n0 + warp_n * 64 + j * 8 + tg * 2);

#pragma unroll
    for (int i = 0; i < 4; i++) {
        int r0 = m0 + warp_m * 64 + i * 16 + grp;
#pragma unroll
        for (int j = 0; j < 8; j++) {
            int n = n0 + warp_n * 64 + j * 8 + tg * 2;
            *(float2*)(out + (size_t)r0 * CC + n) =
                make_float2(acc[i][j][0] + bj[j].x, acc[i][j][1] + bj[j].y);
            *(float2*)(out + (size_t)(r0 + 8) * CC + n) =
                make_float2(acc[i][j][2] + bj[j].x, acc[i][j][3] + bj[j].y);
        }
    }
}

// ============================================================================
// Flash attention fp16: Q tile 128 (8 warps x 16 rows), KV tiles 64, cp.async
// double-buffered, register-resident S/softmax/O, P register-repacked,
// V pre-transposed (B,H,D,T). Fragment loads via ldmatrix. 2 CTAs/SM.
// ============================================================================
#define HLD 72
#define ATT_SMEM ((2 * 64 * HLD + 2 * 64 * HLD + 128 * HLD) * 2)

__global__ __launch_bounds__(256, 2) void attn_kernel(
    const __half* __restrict__ q, const __half* __restrict__ k,
    const __half* __restrict__ v, __half* __restrict__ y)
{
    extern __shared__ __half smh[];
    __half* Ks = smh;                       // 2 x 64 x HLD   [token][d]
    __half* Vs = smh + 2 * 64 * HLD;        // 2 x 64 x HLD   [d][token]
    __half* Qs = smh + 4 * 64 * HLD;        // 128 x HLD      [q][d], reused for out

    const int qt = (gridDim.x - 1) - blockIdx.x;
    const int h  = blockIdx.y;
    const int b  = blockIdx.z;
    const int tid  = threadIdx.x;
    const int w    = tid >> 5;
    const int lane = tid & 31;
    const int grp  = lane >> 2;
    const int tg   = lane & 3;

    const __half* qb  = q + ((size_t)(b * NH + h) * TT + (size_t)qt * 128) * HS;
    const __half* kb0 = k + (size_t)(b * NH + h) * TT * HS;
    const __half* vb0 = v + (size_t)(b * NH + h) * HS * TT;

    const uint32_t ks_addr = smem_u32(Ks);
    const uint32_t vs_addr = smem_u32(Vs);
    const uint32_t qs_addr = smem_u32(Qs);

    const int a_lrow = (lane & 7) + ((lane >> 3) & 1) * 8;
    const int a_lkof = (lane >> 4) * 8;
    const int b_lrow = (lane & 7) + ((lane >> 4) & 1) * 8;
    const int b_lkof = ((lane >> 3) & 1) * 8;

#define KV_ISSUE(KT_, BUF_)                                                     \
    do {                                                                        \
        uint32_t kbase = ks_addr + (uint32_t)(BUF_) * 64 * HLD * 2;             \
        uint32_t vbase = vs_addr + (uint32_t)(BUF_) * 64 * HLD * 2;             \
        _Pragma("unroll")                                                       \
        for (int c = 0; c < 2; c++) {                                           \
            int id = c * 256 + tid;                                             \
            int row = id >> 3, kc = id & 7;                                     \
            cp16(kbase + (row * HLD + kc * 8) * 2,                              \
                 kb0 + ((size_t)(KT_) * 64 + row) * HS + kc * 8);               \
            cp16(vbase + (row * HLD + kc * 8) * 2,                              \
                 vb0 + (size_t)row * TT + (KT_) * 64 + kc * 8);                 \
        }                                                                       \
    } while (0)

    const int nk = 2 * qt + 2;

    KV_ISSUE(0, 0);
    CP_COMMIT();
    // stage Q
#pragma unroll
    for (int c = 0; c < 4; c++) {
        int id = c * 256 + tid;
        int row = id >> 3, kc = id & 7;
        cp16(qs_addr + (row * HLD + kc * 8) * 2, qb + (size_t)row * HS + kc * 8);
    }
    CP_COMMIT();
    CP_WAIT(0);
    __syncthreads();

    const uint32_t qw_addr = qs_addr + (uint32_t)w * 16 * HLD * 2;
    uint32_t qf[4][4];
#pragma unroll
    for (int ks = 0; ks < 4; ks++)
        ldsm_x4(qf[ks][0], qf[ks][1], qf[ks][2], qf[ks][3],
                qw_addr + (a_lrow * HLD + ks * 16 + a_lkof) * 2);

    float oacc[8][4];
#pragma unroll
    for (int j = 0; j < 8; j++)
#pragma unroll
        for (int c = 0; c < 4; c++) oacc[j][c] = 0.0f;

    float m0r = -1e30f, m1r = -1e30f, l0 = 0.0f, l1 = 0.0f;

    const int wrb  = qt * 128 + w * 16;
    const int row0 = wrb + grp;
    const int row1 = row0 + 8;

#pragma unroll 1
    for (int kt = 0; kt < nk; kt++) {
        const int buf = kt & 1;
        if (kt + 1 < nk) { KV_ISSUE(kt + 1, buf ^ 1); CP_COMMIT(); }

        const uint32_t kb = ks_addr + (uint32_t)buf * 64 * HLD * 2;
        const uint32_t vb = vs_addr + (uint32_t)buf * 64 * HLD * 2;

        if (kt * 64 <= wrb + 15) {
            // ---- S = Q K^T
            float sacc[8][4];
#pragma unroll
            for (int j = 0; j < 8; j++)
#pragma unroll
                for (int c = 0; c < 4; c++) sacc[j][c] = 0.0f;

#pragma unroll
            for (int ks = 0; ks < 4; ks++) {
                uint32_t kf[8][2];
#pragma unroll
                for (int j2 = 0; j2 < 4; j2++) {
                    int row = j2 * 16 + b_lrow;
                    ldsm_x4(kf[2 * j2][0], kf[2 * j2][1], kf[2 * j2 + 1][0], kf[2 * j2 + 1][1],
                            kb + (row * HLD + ks * 16 + b_lkof) * 2);
                }
#pragma unroll
                for (int j = 0; j < 8; j++)
                    mma_f16(sacc[j], qf[ks], kf[j][0], kf[j][1]);
            }

            // ---- causal mask
            if (kt * 64 + 63 > wrb) {
#pragma unroll
                for (int j = 0; j < 8; j++) {
#pragma unroll
                    for (int c = 0; c < 2; c++) {
                        int col = kt * 64 + j * 8 + 2 * tg + c;
                        if (col > row0) sacc[j][c]     = -1e30f;
                        if (col > row1) sacc[j][2 + c] = -1e30f;
                    }
                }
            }

            // ---- online softmax (registers)
            float mx0 = -1e30f, mx1 = -1e30f;
#pragma unroll
            for (int j = 0; j < 8; j++) {
                mx0 = fmaxf(mx0, fmaxf(sacc[j][0], sacc[j][1]));
                mx1 = fmaxf(mx1, fmaxf(sacc[j][2], sacc[j][3]));
            }
            mx0 = fmaxf(mx0, __shfl_xor_sync(0xffffffffu, mx0, 1));
            mx0 = fmaxf(mx0, __shfl_xor_sync(0xffffffffu, mx0, 2));
            mx1 = fmaxf(mx1, __shfl_xor_sync(0xffffffffu, mx1, 1));
            mx1 = fmaxf(mx1, __shfl_xor_sync(0xffffffffu, mx1, 2));

            float mn0 = fmaxf(m0r, mx0), mn1 = fmaxf(m1r, mx1);
            float a0 = __expf(m0r - mn0), a1 = __expf(m1r - mn1);
            m0r = mn0; m1r = mn1;

            float s0 = 0.0f, s1 = 0.0f;
#pragma unroll
            for (int j = 0; j < 8; j++) {
                float p;
                p = __expf(sacc[j][0] - mn0); sacc[j][0] = p; s0 += p;
                p = __expf(sacc[j][1] - mn0); sacc[j][1] = p; s0 += p;
                p = __expf(sacc[j][2] - mn1); sacc[j][2] = p; s1 += p;
                p = __expf(sacc[j][3] - mn1); sacc[j][3] = p; s1 += p;
            }
            s0 += __shfl_xor_sync(0xffffffffu, s0, 1);
            s0 += __shfl_xor_sync(0xffffffffu, s0, 2);
            s1 += __shfl_xor_sync(0xffffffffu, s1, 1);
            s1 += __shfl_xor_sync(0xffffffffu, s1, 2);
            l0 = l0 * a0 + s0;
            l1 = l1 * a1 + s1;

#pragma unroll
            for (int j = 0; j < 8; j++) {
                oacc[j][0] *= a0; oacc[j][1] *= a0;
                oacc[j][2] *= a1; oacc[j][3] *= a1;
            }

            // ---- O += P V : P repacked in registers (C-frag -> A-frag)
#pragma unroll
            for (int ks = 0; ks < 4; ks++) {
                uint32_t pa[4];
                pa[0] = pack_h2(sacc[2 * ks][0],     sacc[2 * ks][1]);
                pa[1] = pack_h2(sacc[2 * ks][2],     sacc[2 * ks][3]);
                pa[2] = pack_h2(sacc[2 * ks + 1][0], sacc[2 * ks + 1][1]);
                pa[3] = pack_h2(sacc[2 * ks + 1][2], sacc[2 * ks + 1][3]);
                uint32_t vf[8][2];
#pragma unroll
                for (int j2 = 0; j2 < 4; j2++) {
                    int row = j2 * 16 + b_lrow;
                    ldsm_x4(vf[2 * j2][0], vf[2 * j2][1], vf[2 * j2 + 1][0], vf[2 * j2 + 1][1],
                            vb + (row * HLD + ks * 16 + b_lkof) * 2);
                }
#pragma unroll
                for (int j = 0; j < 8; j++)
                    mma_f16(oacc[j], pa, vf[j][0], vf[j][1]);
            }
        }

        if (kt + 1 < nk) CP_WAIT(0);
        __syncthreads();
    }

    // ---- normalize, write y (B,T,C) fp16 via staging
    float inv0 = 1.0f / l0, inv1 = 1.0f / l1;
    __half* Ow = Qs + w * 16 * HLD;
#pragma unroll
    for (int j = 0; j < 8; j++) {
        *(uint32_t*)(Ow + grp       * HLD + j * 8 + 2 * tg) =
            pack_h2(oacc[j][0] * inv0, oacc[j][1] * inv0);
        *(uint32_t*)(Ow + (grp + 8) * HLD + j * 8 + 2 * tg) =
            pack_h2(oacc[j][2] * inv1, oacc[j][3] * inv1);
    }
    __syncwarp();

    __half* yb = y + ((size_t)b * TT + qt * 128 + w * 16) * CC + h * HS;
#pragma unroll
    for (int idx = lane; idx < 128; idx += 32) {
        int r = idx >> 3, f = idx & 7;
        *(float4*)(yb + (size_t)r * CC + f * 8) = *(const float4*)(Ow + r * HLD + f * 8);
    }
#undef KV_ISSUE
}

// ============================================================================
// launch
// ============================================================================
extern "C" void kernel_launch(void* const* d_in, const int* in_sizes, int n_in,
                              void* d_out, int out_size)
{
    const float* x  = (const float*)d_in[0];
    const float* Wk = (const float*)d_in[1];
    const float* bk = (const float*)d_in[2];
    const float* Wq = (const float*)d_in[3];
    const float* bq = (const float*)d_in[4];
    const float* Wv = (const float*)d_in[5];
    const float* bv = (const float*)d_in[6];
    const float* Wo = (const float*)d_in[7];
    const float* bo = (const float*)d_in[8];
    float* out = (float*)d_out;

    __half *qp, *kp, *vp, *yp, *xc, *wq, *wk, *wv, *wo;
    cudaGetSymbolAddress((void**)&qp, g_q);
    cudaGetSymbolAddress((void**)&kp, g_k);
    cudaGetSymbolAddress((void**)&vp, g_v);
    cudaGetSymbolAddress((void**)&yp, g_y);
    cudaGetSymbolAddress((void**)&xc, g_xc);
    cudaGetSymbolAddress((void**)&wq, g_wq);
    cudaGetSymbolAddress((void**)&wk, g_wk);
    cudaGetSymbolAddress((void**)&wv, g_wv);
    cudaGetSymbolAddress((void**)&wo, g_wo);

    cudaFuncSetAttribute(qkv_gemm_kernel,
                         cudaFuncAttributeMaxDynamicSharedMemorySize, GEMM_SMEM);
    cudaFuncSetAttribute(out_gemm_kernel,
                         cudaFuncAttributeMaxDynamicSharedMemorySize, GEMM_SMEM);
    cudaFuncSetAttribute(attn_kernel,
                         cudaFuncAttributeMaxDynamicSharedMemorySize, ATT_SMEM);

    // prep
    int nx4 = (BB * TT * CC) / 4;
    round_half_kernel<<<nx4 / 256, 256>>>(x, xc, nx4);
    dim3 tgrid(CC / 32, CC / 32), tblk(32, 8);
    transpose_w_kernel<<<tgrid, tblk>>>(Wq, wq);
    transpose_w_kernel<<<tgrid, tblk>>>(Wk, wk);
    transpose_w_kernel<<<tgrid, tblk>>>(Wv, wv);
    transpose_w_kernel<<<tgrid, tblk>>>(Wo, wo);

    dim3 qkvgrid(CC / 128, (BB * TT) / 128, 3);
    qkv_gemm_kernel<<<qkvgrid, 128, GEMM_SMEM>>>(xc, wq, wk, wv, bq, bk, bv,
                                                 qp, kp, vp);

    dim3 agrid(TT / 128, NH, BB);
    attn_kernel<<<agrid, 256, ATT_SMEM>>>(qp, kp, vp, yp);

    dim3 ogrid(CC / 128, (BB * TT) / 128);
    out_gemm_kernel<<<ogrid, 128, GEMM_SMEM>>>(yp, wo, bo, out);
}